// round 6
// baseline (speedup 1.0000x reference)
#include <cuda_runtime.h>
#include <cuda_bf16.h>
#include <math.h>
#include <cstdint>

#define Bn 8
#define Sn 1024
#define Cn 1024
#define Hn 16
#define Dn 64
#define Mn (Bn*Sn)        // 8192
#define N1 (3*Cn)         // 3072
#define KP (3*Cn)         // extended K for hi/lo-split GEMM

// ---- scratch (static device globals; no allocation) ----
__device__ float g_qkv[(size_t)Mn * N1];            // (B,S,3C)
__device__ __nv_bfloat16 g_qh[(size_t)Bn*Hn*Sn*Dn]; // split q/k/v (B,H,S,D)
__device__ __nv_bfloat16 g_ql[(size_t)Bn*Hn*Sn*Dn];
__device__ __nv_bfloat16 g_kh[(size_t)Bn*Hn*Sn*Dn];
__device__ __nv_bfloat16 g_kl[(size_t)Bn*Hn*Sn*Dn];
__device__ __nv_bfloat16 g_vh[(size_t)Bn*Hn*Sn*Dn];
__device__ __nv_bfloat16 g_vl[(size_t)Bn*Hn*Sn*Dn];
__device__ __nv_bfloat16 g_A3[(size_t)Mn * KP];     // split A for GEMMs
__device__ __nv_bfloat16 g_B3[(size_t)N1 * KP];     // split B^T for GEMMs

// ============================================================
// helpers
// ============================================================
__device__ __forceinline__ uint32_t smem_u32(const void* p) {
    uint32_t a;
    asm("{ .reg .u64 t; cvta.to.shared.u64 t, %1; cvt.u32.u64 %0, t; }"
        : "=r"(a) : "l"(p));
    return a;
}
__device__ __forceinline__ void cpa16(uint32_t s, const void* g) {
    asm volatile("cp.async.cg.shared.global [%0], [%1], 16;" :: "r"(s), "l"(g));
}
__device__ __forceinline__ void ldm4(uint32_t addr, uint32_t& r0, uint32_t& r1,
                                     uint32_t& r2, uint32_t& r3) {
    asm volatile("ldmatrix.sync.aligned.m8n8.x4.shared.b16 {%0,%1,%2,%3}, [%4];"
                 : "=r"(r0), "=r"(r1), "=r"(r2), "=r"(r3) : "r"(addr));
}
__device__ __forceinline__ void ldm4t(uint32_t addr, uint32_t& r0, uint32_t& r1,
                                      uint32_t& r2, uint32_t& r3) {
    asm volatile("ldmatrix.sync.aligned.m8n8.x4.trans.shared.b16 {%0,%1,%2,%3}, [%4];"
                 : "=r"(r0), "=r"(r1), "=r"(r2), "=r"(r3) : "r"(addr));
}
__device__ __forceinline__ void mma_bf16(float* d, const uint32_t* a,
                                         uint32_t b0, uint32_t b1) {
    asm volatile(
        "mma.sync.aligned.m16n8k16.row.col.f32.bf16.bf16.f32 "
        "{%0,%1,%2,%3}, {%4,%5,%6,%7}, {%8,%9}, {%0,%1,%2,%3};"
        : "+f"(d[0]), "+f"(d[1]), "+f"(d[2]), "+f"(d[3])
        : "r"(a[0]), "r"(a[1]), "r"(a[2]), "r"(a[3]), "r"(b0), "r"(b1));
}
__device__ __forceinline__ float ex2(float x) {
    float r;
    asm("ex2.approx.f32 %0, %1;" : "=f"(r) : "f"(x));
    return r;
}
__device__ __forceinline__ void split2(float v, __nv_bfloat16& h, __nv_bfloat16& l) {
    h = __float2bfloat16(v);
    l = __float2bfloat16(v - __bfloat162float(h));
}
__device__ __forceinline__ uint32_t packbf(__nv_bfloat16 a, __nv_bfloat16 b) {
    __nv_bfloat162 t(a, b);
    return *(uint32_t*)&t;
}

// ============================================================
// Split conversions for the dense GEMMs
// A3 = [hi | lo | hi], B3 = [hi | hi | lo]  (K'=3K)
// ============================================================
__global__ __launch_bounds__(256) void conv_A(const float* __restrict__ A,
                                              __nv_bfloat16* __restrict__ A3, int Kdim)
{
    int idx = blockIdx.x * 256 + threadIdx.x;
    int r = idx / Kdim, k = idx - r * Kdim;
    float v = A[idx];
    __nv_bfloat16 hi, lo;
    split2(v, hi, lo);
    size_t base = (size_t)r * (3 * Kdim);
    A3[base + k] = hi;
    A3[base + Kdim + k] = lo;
    A3[base + 2 * Kdim + k] = hi;
}

__global__ __launch_bounds__(256) void conv_B(const float* __restrict__ W,
                                              __nv_bfloat16* __restrict__ B3,
                                              int Kdim, int Ndim)
{
    __shared__ float t[32][33];
    int k0 = blockIdx.x * 32, n0 = blockIdx.y * 32;
    int tx = threadIdx.x & 31, ty = threadIdx.x >> 5;
    #pragma unroll
    for (int i = 0; i < 4; i++)
        t[ty + i * 8][tx] = W[(size_t)(k0 + ty + i * 8) * Ndim + n0 + tx];
    __syncthreads();
    #pragma unroll
    for (int i = 0; i < 4; i++) {
        int n = ty + i * 8;
        float v = t[tx][n];
        __nv_bfloat16 hi, lo;
        split2(v, hi, lo);
        size_t base = (size_t)(n0 + n) * (3 * Kdim);
        B3[base + k0 + tx] = hi;
        B3[base + Kdim + k0 + tx] = hi;
        B3[base + 2 * Kdim + k0 + tx] = lo;
    }
}

// ============================================================
// HMMA bf16 GEMM: 3-stage cp.async pipeline, single sync/iter.
// 128x128 CTA tile, K-tile 64, 8 warps, warp tile 64x32.
// ============================================================
#define KT 64
#define ROWB 144
#define TILEB (128 * ROWB)
#define NSTG 3
#define GM_SMEM (NSTG * 2 * TILEB)     // 110592 B -> 2 CTAs/SM

__global__ __launch_bounds__(256, 2) void gemm_mma(
    const __nv_bfloat16* __restrict__ A, const __nv_bfloat16* __restrict__ B,
    const float* __restrict__ bias, float* __restrict__ C,
    int Ndim, int Kp)
{
    extern __shared__ char smraw[];
    const uint32_t sb = smem_u32(smraw);
    const int tid = threadIdx.x;
    const int wid = tid >> 5, lane = tid & 31;
    const int brow = blockIdx.y * 128, bcol = blockIdx.x * 128;
    const int warpM = (wid >> 2) * 64;
    const int warpN = (wid & 3) * 32;

    float acc[4][4][4];
    #pragma unroll
    for (int i = 0; i < 4; i++)
        #pragma unroll
        for (int j = 0; j < 4; j++)
            #pragma unroll
            for (int e = 0; e < 4; e++) acc[i][j][e] = 0.f;

    const int NT = Kp / KT;

    auto load_tile = [&](int kc, int buf) {
        uint32_t ab = sb + buf * (2 * TILEB);
        uint32_t bb = ab + TILEB;
        const __nv_bfloat16* Ag = A + (size_t)brow * Kp + kc * KT;
        const __nv_bfloat16* Bg = B + (size_t)bcol * Kp + kc * KT;
        #pragma unroll
        for (int i = 0; i < 4; i++) {
            int slot = i * 256 + tid;
            int r = slot >> 3, c = slot & 7;
            uint32_t so = (uint32_t)(r * ROWB + c * 16);
            cpa16(ab + so, Ag + (size_t)r * Kp + c * 8);
            cpa16(bb + so, Bg + (size_t)r * Kp + c * 8);
        }
        asm volatile("cp.async.commit_group;" ::: "memory");
    };

    // prologue: 2 stages in flight
    load_tile(0, 0);
    load_tile(1, 1);

    const int lm = lane & 15, lh = lane >> 4;

    for (int kt = 0; kt < NT; kt++) {
        if (kt + 1 < NT)
            asm volatile("cp.async.wait_group 1;" ::: "memory");
        else
            asm volatile("cp.async.wait_group 0;" ::: "memory");
        __syncthreads();

        // issue next-next stage (safe: all warps done reading that slot)
        if (kt + 2 < NT) {
            int buf = (kt + 2) % NSTG;
            load_tile(kt + 2, buf);
        }

        uint32_t ab = sb + (kt % NSTG) * (2 * TILEB);
        uint32_t bb = ab + TILEB;
        uint32_t aAddr = ab + (uint32_t)((warpM + lm) * ROWB + lh * 16);
        uint32_t bAddr = bb + (uint32_t)((warpN + lm) * ROWB + lh * 16);

        #pragma unroll
        for (int ks = 0; ks < 4; ks++) {
            uint32_t afr[4][4];
            #pragma unroll
            for (int mf = 0; mf < 4; mf++)
                ldm4(aAddr + mf * 16 * ROWB + ks * 32,
                     afr[mf][0], afr[mf][1], afr[mf][2], afr[mf][3]);
            uint32_t bfr[4][2];
            #pragma unroll
            for (int nb = 0; nb < 2; nb++) {
                uint32_t r0, r1, r2, r3;
                ldm4(bAddr + nb * 16 * ROWB + ks * 32, r0, r1, r2, r3);
                bfr[nb * 2 + 0][0] = r0; bfr[nb * 2 + 0][1] = r2;
                bfr[nb * 2 + 1][0] = r1; bfr[nb * 2 + 1][1] = r3;
            }
            #pragma unroll
            for (int mf = 0; mf < 4; mf++)
                #pragma unroll
                for (int nf = 0; nf < 4; nf++)
                    mma_bf16(acc[mf][nf], afr[mf], bfr[nf][0], bfr[nf][1]);
        }
    }

    #pragma unroll
    for (int mf = 0; mf < 4; mf++) {
        int grow = brow + warpM + mf * 16 + (lane >> 2);
        #pragma unroll
        for (int nf = 0; nf < 4; nf++) {
            int gcol = bcol + warpN + nf * 8 + (lane & 3) * 2;
            float bx = bias[gcol], by = bias[gcol + 1];
            float* d = acc[mf][nf];
            float2 v0 = {d[0] + bx, d[1] + by};
            float2 v1 = {d[2] + bx, d[3] + by};
            *(float2*)&C[(size_t)grow * Ndim + gcol] = v0;
            *(float2*)&C[(size_t)(grow + 8) * Ndim + gcol] = v1;
        }
    }
}

// ============================================================
// RoPE + hi/lo split scatter (q pre-scaled by 0.125*log2 e)
// ============================================================
__global__ __launch_bounds__(256) void rope_split_kernel()
{
    int idx = blockIdx.x * blockDim.x + threadIdx.x;
    int i = idx & 31;
    int s = (idx >> 5)  & (Sn - 1);
    int h = (idx >> 15) & (Hn - 1);
    int b =  idx >> 19;

    const float* row = g_qkv + (size_t)(b * Sn + s) * N1;
    int base = h * Dn;

    float inv = expf(-(logf(10000.f) / Dn) * (2.f * i));
    float ang = (float)s * inv;
    float sn, cs;
    sincosf(ang, &sn, &cs);

    float q1 = row[0*Cn + base + i];
    float q2 = row[0*Cn + base + i + 32];
    float k1 = row[1*Cn + base + i];
    float k2 = row[1*Cn + base + i + 32];
    float v1 = row[2*Cn + base + i];
    float v2 = row[2*Cn + base + i + 32];

    const float QS = 0.18033688011112042f;  // 0.125 * log2(e)

    float qa = (q1 * cs - q2 * sn) * QS;
    float qb = (q2 * cs + q1 * sn) * QS;
    float ka = k1 * cs - k2 * sn;
    float kb = k2 * cs + k1 * sn;

    size_t o = ((size_t)(b * Hn + h) * Sn + s) * Dn;
    __nv_bfloat16 hh, ll;
    split2(qa, hh, ll); g_qh[o + i] = hh;      g_ql[o + i] = ll;
    split2(qb, hh, ll); g_qh[o + i + 32] = hh; g_ql[o + i + 32] = ll;
    split2(ka, hh, ll); g_kh[o + i] = hh;      g_kl[o + i] = ll;
    split2(kb, hh, ll); g_kh[o + i + 32] = hh; g_kl[o + i + 32] = ll;
    split2(v1, hh, ll); g_vh[o + i] = hh;      g_vl[o + i] = ll;
    split2(v2, hh, ll); g_vh[o + i + 32] = hh; g_vl[o + i + 32] = ll;
}

// ============================================================
// HMMA flash attention with 3-product hi/lo splits.
// ============================================================
#define AT_ROWB 144
#define AT_TILE (128 * AT_ROWB)
#define AT_STAGE (4 * AT_TILE)
#define AT_SMEM (2 * AT_TILE + 2 * AT_STAGE)

__global__ __launch_bounds__(256, 1) void attn_mma()
{
    extern __shared__ char smraw[];
    const uint32_t sb = smem_u32(smraw);
    const int tid = threadIdx.x, wid = tid >> 5, lane = tid & 31;
    const int bh = blockIdx.y;
    const int q0 = blockIdx.x * 128;
    const size_t bhoff = (size_t)bh * Sn * Dn;

    const uint32_t qhi_s = sb;
    const uint32_t qlo_s = sb + AT_TILE;
    const uint32_t stage0 = sb + 2 * AT_TILE;

    {
        const __nv_bfloat16* Qh = g_qh + bhoff + (size_t)q0 * Dn;
        const __nv_bfloat16* Ql = g_ql + bhoff + (size_t)q0 * Dn;
        #pragma unroll
        for (int i = 0; i < 4; i++) {
            int slot = i * 256 + tid;
            int r = slot >> 3, c = slot & 7;
            uint32_t so = (uint32_t)(r * AT_ROWB + c * 16);
            cpa16(qhi_s + so, Qh + (size_t)r * Dn + c * 8);
            cpa16(qlo_s + so, Ql + (size_t)r * Dn + c * 8);
        }
    }
    auto load_kv = [&](int t, int buf) {
        uint32_t st = stage0 + buf * AT_STAGE;
        const __nv_bfloat16* Kh = g_kh + bhoff + (size_t)t * 128 * Dn;
        const __nv_bfloat16* Kl = g_kl + bhoff + (size_t)t * 128 * Dn;
        const __nv_bfloat16* Vh = g_vh + bhoff + (size_t)t * 128 * Dn;
        const __nv_bfloat16* Vl = g_vl + bhoff + (size_t)t * 128 * Dn;
        #pragma unroll
        for (int i = 0; i < 4; i++) {
            int slot = i * 256 + tid;
            int r = slot >> 3, c = slot & 7;
            uint32_t so = (uint32_t)(r * AT_ROWB + c * 16);
            size_t go = (size_t)r * Dn + c * 8;
            cpa16(st + so, Kh + go);
            cpa16(st + AT_TILE + so, Kl + go);
            cpa16(st + 2 * AT_TILE + so, Vh + go);
            cpa16(st + 3 * AT_TILE + so, Vl + go);
        }
        asm volatile("cp.async.commit_group;" ::: "memory");
    };
    load_kv(0, 0);

    asm volatile("cp.async.wait_group 0;" ::: "memory");
    __syncthreads();

    const int lm = lane & 15, lh = lane >> 4;
    uint32_t qh[4][4], ql[4][4];
    {
        uint32_t a = (uint32_t)((wid * 16 + lm) * AT_ROWB + lh * 16);
        #pragma unroll
        for (int ks = 0; ks < 4; ks++) {
            ldm4(qhi_s + a + ks * 32, qh[ks][0], qh[ks][1], qh[ks][2], qh[ks][3]);
            ldm4(qlo_s + a + ks * 32, ql[ks][0], ql[ks][1], ql[ks][2], ql[ks][3]);
        }
    }

    float o[8][4];
    #pragma unroll
    for (int i = 0; i < 8; i++)
        #pragma unroll
        for (int e = 0; e < 4; e++) o[i][e] = 0.f;
    float m0 = -1e30f, m1 = -1e30f, ps0 = 0.f, ps1 = 0.f;

    for (int t = 0; t < 8; t++) {
        if (t > 0) {
            asm volatile("cp.async.wait_group 0;" ::: "memory");
            __syncthreads();
        }
        if (t < 7) load_kv(t + 1, (t + 1) & 1);

        uint32_t st = stage0 + (t & 1) * AT_STAGE;
        uint32_t kh_s = st, kl_s = st + AT_TILE;
        uint32_t vh_s = st + 2 * AT_TILE, vl_s = st + 3 * AT_TILE;

        float sc[16][4];
        #pragma unroll
        for (int f = 0; f < 16; f++)
            #pragma unroll
            for (int e = 0; e < 4; e++) sc[f][e] = 0.f;

        uint32_t bbase = (uint32_t)(lm * AT_ROWB + lh * 16);
        #pragma unroll
        for (int nb = 0; nb < 8; nb++) {
            uint32_t ah = kh_s + bbase + nb * 16 * AT_ROWB;
            uint32_t al = kl_s + bbase + nb * 16 * AT_ROWB;
            #pragma unroll
            for (int ks = 0; ks < 4; ks++) {
                uint32_t h0, h1, h2, h3, l0, l1, l2, l3;
                ldm4(ah + ks * 32, h0, h1, h2, h3);
                ldm4(al + ks * 32, l0, l1, l2, l3);
                mma_bf16(sc[2 * nb],     qh[ks], h0, h2);
                mma_bf16(sc[2 * nb],     ql[ks], h0, h2);
                mma_bf16(sc[2 * nb],     qh[ks], l0, l2);
                mma_bf16(sc[2 * nb + 1], qh[ks], h1, h3);
                mma_bf16(sc[2 * nb + 1], ql[ks], h1, h3);
                mma_bf16(sc[2 * nb + 1], qh[ks], l1, l3);
            }
        }

        float mx0 = -1e30f, mx1 = -1e30f;
        #pragma unroll
        for (int f = 0; f < 16; f++) {
            mx0 = fmaxf(mx0, fmaxf(sc[f][0], sc[f][1]));
            mx1 = fmaxf(mx1, fmaxf(sc[f][2], sc[f][3]));
        }
        mx0 = fmaxf(mx0, __shfl_xor_sync(0xffffffffu, mx0, 1));
        mx0 = fmaxf(mx0, __shfl_xor_sync(0xffffffffu, mx0, 2));
        mx1 = fmaxf(mx1, __shfl_xor_sync(0xffffffffu, mx1, 1));
        mx1 = fmaxf(mx1, __shfl_xor_sync(0xffffffffu, mx1, 2));

        float mn0 = fmaxf(m0, mx0), mn1 = fmaxf(m1, mx1);
        float f0 = ex2(m0 - mn0), f1 = ex2(m1 - mn1);
        m0 = mn0; m1 = mn1;
        ps0 *= f0; ps1 *= f1;
        #pragma unroll
        for (int nf = 0; nf < 8; nf++) {
            o[nf][0] *= f0; o[nf][1] *= f0;
            o[nf][2] *= f1; o[nf][3] *= f1;
        }

        uint32_t pa_hi[8][4], pa_lo[8][4];
        #pragma unroll
        for (int t2 = 0; t2 < 8; t2++) {
            #pragma unroll
            for (int half = 0; half < 2; half++) {
                int f = 2 * t2 + half;
                float p0 = ex2(sc[f][0] - m0);
                float p1 = ex2(sc[f][1] - m0);
                float p2 = ex2(sc[f][2] - m1);
                float p3 = ex2(sc[f][3] - m1);
                ps0 += p0 + p1; ps1 += p2 + p3;
                __nv_bfloat16 h0, l0, h1, l1, h2, l2, h3, l3;
                split2(p0, h0, l0); split2(p1, h1, l1);
                split2(p2, h2, l2); split2(p3, h3, l3);
                pa_hi[t2][half * 2 + 0] = packbf(h0, h1);
                pa_hi[t2][half * 2 + 1] = packbf(h2, h3);
                pa_lo[t2][half * 2 + 0] = packbf(l0, l1);
                pa_lo[t2][half * 2 + 1] = packbf(l2, l3);
            }
        }

        #pragma unroll
        for (int t2 = 0; t2 < 8; t2++) {
            uint32_t vrow = (uint32_t)((t2 * 16 + lm) * AT_ROWB + lh * 16);
            #pragma unroll
            for (int dn = 0; dn < 4; dn++) {
                uint32_t h0, h1, h2, h3, l0, l1, l2, l3;
                ldm4t(vh_s + vrow + dn * 32, h0, h1, h2, h3);
                ldm4t(vl_s + vrow + dn * 32, l0, l1, l2, l3);
                mma_bf16(o[2 * dn],     pa_hi[t2], h0, h1);
                mma_bf16(o[2 * dn],     pa_lo[t2], h0, h1);
                mma_bf16(o[2 * dn],     pa_hi[t2], l0, l1);
                mma_bf16(o[2 * dn + 1], pa_hi[t2], h2, h3);
                mma_bf16(o[2 * dn + 1], pa_lo[t2], h2, h3);
                mma_bf16(o[2 * dn + 1], pa_hi[t2], l2, l3);
            }
        }
    }

    ps0 += __shfl_xor_sync(0xffffffffu, ps0, 1);
    ps0 += __shfl_xor_sync(0xffffffffu, ps0, 2);
    ps1 += __shfl_xor_sync(0xffffffffu, ps1, 1);
    ps1 += __shfl_xor_sync(0xffffffffu, ps1, 2);
    float inv0 = 1.f / ps0, inv1 = 1.f / ps1;

    const int bidx = bh >> 4, hidx = bh & 15;
    const int grow = bidx * Sn + q0 + wid * 16 + (lane >> 2);

    #pragma unroll
    for (int nf = 0; nf < 8; nf++) {
        int col = hidx * 64 + nf * 8 + (lane & 3) * 2;
        float v0 = o[nf][0] * inv0, v1 = o[nf][1] * inv0;
        float v2 = o[nf][2] * inv1, v3 = o[nf][3] * inv1;
        __nv_bfloat16 h0, l0, h1, l1, h2, l2, h3, l3;
        split2(v0, h0, l0); split2(v1, h1, l1);
        split2(v2, h2, l2); split2(v3, h3, l3);
        uint32_t hp0 = packbf(h0, h1), lp0 = packbf(l0, l1);
        uint32_t hp1 = packbf(h2, h3), lp1 = packbf(l2, l3);
        size_t r0 = (size_t)grow * KP + col;
        size_t r1 = (size_t)(grow + 8) * KP + col;
        *(uint32_t*)&g_A3[r0]        = hp0;
        *(uint32_t*)&g_A3[r0 + 1024] = lp0;
        *(uint32_t*)&g_A3[r0 + 2048] = hp0;
        *(uint32_t*)&g_A3[r1]        = hp1;
        *(uint32_t*)&g_A3[r1 + 1024] = lp1;
        *(uint32_t*)&g_A3[r1 + 2048] = hp1;
    }
}

// ============================================================
// Launch
// ============================================================
extern "C" void kernel_launch(void* const* d_in, const int* in_sizes, int n_in,
                              void* d_out, int out_size)
{
    const float* x      = (const float*)d_in[0];
    const float* W_qkv  = (const float*)d_in[1];
    const float* b_qkv  = (const float*)d_in[2];
    const float* W_proj = (const float*)d_in[3];
    const float* b_proj = (const float*)d_in[4];
    float* out = (float*)d_out;

    cudaFuncSetAttribute(gemm_mma, cudaFuncAttributeMaxDynamicSharedMemorySize, GM_SMEM);
    cudaFuncSetAttribute(attn_mma, cudaFuncAttributeMaxDynamicSharedMemorySize, AT_SMEM);

    float* p_qkv;
    __nv_bfloat16 *p_A3, *p_B3;
    cudaGetSymbolAddress((void**)&p_qkv, g_qkv);
    cudaGetSymbolAddress((void**)&p_A3, g_A3);
    cudaGetSymbolAddress((void**)&p_B3, g_B3);

    // 1) split-convert x and W_qkv
    conv_A<<<(Mn * Cn) / 256, 256>>>(x, p_A3, Cn);
    {
        dim3 g(Cn / 32, N1 / 32);
        conv_B<<<g, 256>>>(W_qkv, p_B3, Cn, N1);
    }
    // 2) QKV GEMM (HMMA)
    {
        dim3 g(N1 / 128, Mn / 128);
        gemm_mma<<<g, 256, GM_SMEM>>>(p_A3, p_B3, b_qkv, p_qkv, N1, KP);
    }
    // 3) RoPE + hi/lo split
    rope_split_kernel<<<(Bn * Hn * Sn * 32) / 256, 256>>>();
    // 4) HMMA flash attention -> writes split A3 directly
    {
        dim3 g(Sn / 128, Bn * Hn);
        attn_mma<<<g, 256, AT_SMEM>>>();
    }
    // 5) split-convert W_proj
    {
        dim3 g(Cn / 32, Cn / 32);
        conv_B<<<g, 256>>>(W_proj, p_B3, Cn, Cn);
    }
    // 6) output projection (HMMA)
    {
        dim3 g(Cn / 128, Mn / 128);
        gemm_mma<<<g, 256, GM_SMEM>>>(p_A3, p_B3, b_proj, out, Cn, KP);
    }
}

// round 8
// speedup vs baseline: 1.0077x; 1.0077x over previous
#include <cuda_runtime.h>
#include <cuda_bf16.h>
#include <math.h>
#include <cstdint>

#define Bn 8
#define Sn 1024
#define Cn 1024
#define Hn 16
#define Dn 64
#define Mn (Bn*Sn)
#define N1 (3*Cn)
#define KP (3*Cn)

__device__ float g_qkv[(size_t)Mn * N1];
__device__ __nv_bfloat16 g_qh[(size_t)Bn*Hn*Sn*Dn];
__device__ __nv_bfloat16 g_ql[(size_t)Bn*Hn*Sn*Dn];
__device__ __nv_bfloat16 g_kh[(size_t)Bn*Hn*Sn*Dn];
__device__ __nv_bfloat16 g_kl[(size_t)Bn*Hn*Sn*Dn];
__device__ __nv_bfloat16 g_vh[(size_t)Bn*Hn*Sn*Dn];
__device__ __nv_bfloat16 g_vl[(size_t)Bn*Hn*Sn*Dn];
__device__ __nv_bfloat16 g_A3[(size_t)Mn * KP];
__device__ __nv_bfloat16 g_B3[(size_t)N1 * KP];     // qkv weights split
__device__ __nv_bfloat16 g_B3p[(size_t)Cn * KP];    // proj weights split

__device__ __forceinline__ uint32_t smem_u32(const void* p) {
    uint32_t a;
    asm("{ .reg .u64 t; cvta.to.shared.u64 t, %1; cvt.u32.u64 %0, t; }" : "=r"(a) : "l"(p));
    return a;
}
__device__ __forceinline__ void cpa16(uint32_t s, const void* g) {
    asm volatile("cp.async.cg.shared.global [%0], [%1], 16;" :: "r"(s), "l"(g));
}
__device__ __forceinline__ void ldm4(uint32_t a, uint32_t& r0, uint32_t& r1, uint32_t& r2, uint32_t& r3) {
    asm volatile("ldmatrix.sync.aligned.m8n8.x4.shared.b16 {%0,%1,%2,%3}, [%4];"
                 : "=r"(r0), "=r"(r1), "=r"(r2), "=r"(r3) : "r"(a));
}
__device__ __forceinline__ void ldm4t(uint32_t a, uint32_t& r0, uint32_t& r1, uint32_t& r2, uint32_t& r3) {
    asm volatile("ldmatrix.sync.aligned.m8n8.x4.trans.shared.b16 {%0,%1,%2,%3}, [%4];"
                 : "=r"(r0), "=r"(r1), "=r"(r2), "=r"(r3) : "r"(a));
}
__device__ __forceinline__ void mma_bf16(float* d, const uint32_t* a, uint32_t b0, uint32_t b1) {
    asm volatile("mma.sync.aligned.m16n8k16.row.col.f32.bf16.bf16.f32 "
        "{%0,%1,%2,%3}, {%4,%5,%6,%7}, {%8,%9}, {%0,%1,%2,%3};"
        : "+f"(d[0]), "+f"(d[1]), "+f"(d[2]), "+f"(d[3])
        : "r"(a[0]), "r"(a[1]), "r"(a[2]), "r"(a[3]), "r"(b0), "r"(b1));
}
__device__ __forceinline__ float ex2(float x) { float r; asm("ex2.approx.f32 %0, %1;" : "=f"(r) : "f"(x)); return r; }
__device__ __forceinline__ void split2(float v, __nv_bfloat16& h, __nv_bfloat16& l) {
    h = __float2bfloat16(v);
    l = __float2bfloat16(v - __bfloat162float(h));
}
__device__ __forceinline__ uint32_t packbf(__nv_bfloat16 a, __nv_bfloat16 b) {
    __nv_bfloat162 t(a, b); return *(uint32_t*)&t;
}

#define MBAR_INIT(a, n) asm volatile("mbarrier.init.shared.b64 [%0], %1;" :: "r"(a), "r"(n) : "memory")
#define MBAR_ARRIVE(a)  asm volatile("mbarrier.arrive.shared.b64 _, [%0];" :: "r"(a) : "memory")
// .noinc: consume one of the pre-initialized expected arrivals (default form
// is self-balancing inc+dec and NEVER flips the barrier -> round-7 deadlock)
#define MBAR_ARRIVE_CP(a) asm volatile("cp.async.mbarrier.arrive.noinc.shared::cta.b64 [%0];" :: "r"(a) : "memory")
#define MBAR_WAIT(mb, ph) do { \
    uint32_t _m = (mb); uint32_t _p = (ph); uint32_t _d; \
    asm volatile("{ .reg .pred p; mbarrier.try_wait.parity.acquire.cta.shared::cta.b64 p, [%1], %2;" \
                 " selp.b32 %0,1,0,p; }" : "=r"(_d) : "r"(_m), "r"(_p) : "memory"); \
    if (!_d) { \
        asm volatile("{ .reg .pred P1; WL_%=:" \
                     " mbarrier.try_wait.parity.acquire.cta.shared::cta.b64 P1, [%0], %1, 0x989680;" \
                     " @P1 bra.uni WD_%=; bra.uni WL_%=; WD_%=: }" :: "r"(_m), "r"(_p) : "memory"); \
    } \
} while (0)

// ============ split conversions ============
__global__ __launch_bounds__(256) void conv_A(const float* __restrict__ A,
                                              __nv_bfloat16* __restrict__ A3, int Kdim)
{
    int idx = blockIdx.x * 256 + threadIdx.x;
    int r = idx / Kdim, k = idx - r * Kdim;
    float v = A[idx];
    __nv_bfloat16 hi, lo; split2(v, hi, lo);
    size_t base = (size_t)r * (3 * Kdim);
    A3[base + k] = hi; A3[base + Kdim + k] = lo; A3[base + 2 * Kdim + k] = hi;
}

__global__ __launch_bounds__(256) void conv_B(const float* __restrict__ W,
                                              __nv_bfloat16* __restrict__ B3,
                                              int Kdim, int Ndim)
{
    __shared__ float t[32][33];
    int k0 = blockIdx.x * 32, n0 = blockIdx.y * 32;
    int tx = threadIdx.x & 31, ty = threadIdx.x >> 5;
    #pragma unroll
    for (int i = 0; i < 4; i++)
        t[ty + i * 8][tx] = W[(size_t)(k0 + ty + i * 8) * Ndim + n0 + tx];
    __syncthreads();
    #pragma unroll
    for (int i = 0; i < 4; i++) {
        int n = ty + i * 8;
        float v = t[tx][n];
        __nv_bfloat16 hi, lo; split2(v, hi, lo);
        size_t base = (size_t)(n0 + n) * (3 * Kdim);
        B3[base + k0 + tx] = hi;
        B3[base + Kdim + k0 + tx] = hi;
        B3[base + 2 * Kdim + k0 + tx] = lo;
    }
}

// ============ warp-specialized HMMA GEMM ============
// 288 thr: warps 0-7 consumers (64x32 tiles), warp 8 producer.
// 5 stages, mbarrier full/empty, no CTA syncs in mainloop.
#define KT 64
#define ROWB 144
#define TILEB (128 * ROWB)
#define NSTG 5
#define GM_SMEM (1024 + NSTG * 2 * TILEB)   // 185344 B

__global__ __launch_bounds__(288, 1) void gemm_mma(
    const __nv_bfloat16* __restrict__ A, const __nv_bfloat16* __restrict__ B,
    const float* __restrict__ bias, float* __restrict__ C,
    int Ndim, int Kp)
{
    extern __shared__ char smraw[];
    const uint32_t sb = smem_u32(smraw);
    const uint32_t dat = sb + 1024;
    const int tid = threadIdx.x;
    const int wid = tid >> 5, lane = tid & 31;
    const int brow = blockIdx.y * 128, bcol = blockIdx.x * 128;
    const int NT = Kp / KT;

    if (tid == 0) {
        #pragma unroll
        for (int s = 0; s < NSTG; s++) {
            MBAR_INIT(sb + s * 16, 32);     // full: 32 producer-lane cp arrivals
            MBAR_INIT(sb + s * 16 + 8, 8);  // empty: 8 consumer warps
        }
    }
    __syncthreads();

    if (wid == 8) {
        // -------- producer --------
        int pst = 0, pph = 1;
        for (int kt = 0; kt < NT; kt++) {
            MBAR_WAIT(sb + pst * 16 + 8, pph);
            const __nv_bfloat16* Ag = A + (size_t)brow * Kp + kt * KT;
            const __nv_bfloat16* Bg = B + (size_t)bcol * Kp + kt * KT;
            uint32_t ab = dat + pst * (2 * TILEB);
            #pragma unroll
            for (int i = 0; i < 32; i++) {
                int chunk = lane + i * 32;          // 0..1023
                int r = chunk >> 3, c = chunk & 7;
                uint32_t so = (uint32_t)(r * ROWB + c * 16);
                cpa16(ab + so, Ag + (size_t)r * Kp + c * 8);
                cpa16(ab + TILEB + so, Bg + (size_t)r * Kp + c * 8);
            }
            MBAR_ARRIVE_CP(sb + pst * 16);
            pst++; if (pst == NSTG) { pst = 0; pph ^= 1; }
        }
        return;
    }

    // -------- consumers --------
    const int warpM = (wid >> 2) * 64;
    const int warpN = (wid & 3) * 32;
    const int lm = lane & 15, lh = lane >> 4;

    float acc[4][4][4];
    #pragma unroll
    for (int i = 0; i < 4; i++)
        #pragma unroll
        for (int j = 0; j < 4; j++)
            #pragma unroll
            for (int e = 0; e < 4; e++) acc[i][j][e] = 0.f;

    int cst = 0, cph = 0;
    for (int kt = 0; kt < NT; kt++) {
        MBAR_WAIT(sb + cst * 16, cph);

        uint32_t ab = dat + cst * (2 * TILEB);
        uint32_t bb = ab + TILEB;
        uint32_t aAddr = ab + (uint32_t)((warpM + lm) * ROWB + lh * 16);
        uint32_t bAddr = bb + (uint32_t)((warpN + lm) * ROWB + lh * 16);

        #pragma unroll
        for (int ks = 0; ks < 4; ks++) {
            uint32_t afr[4][4];
            #pragma unroll
            for (int mf = 0; mf < 4; mf++)
                ldm4(aAddr + mf * 16 * ROWB + ks * 32,
                     afr[mf][0], afr[mf][1], afr[mf][2], afr[mf][3]);
            uint32_t bfr[4][2];
            #pragma unroll
            for (int nb = 0; nb < 2; nb++) {
                uint32_t r0, r1, r2, r3;
                ldm4(bAddr + nb * 16 * ROWB + ks * 32, r0, r1, r2, r3);
                bfr[nb * 2 + 0][0] = r0; bfr[nb * 2 + 0][1] = r2;
                bfr[nb * 2 + 1][0] = r1; bfr[nb * 2 + 1][1] = r3;
            }
            #pragma unroll
            for (int mf = 0; mf < 4; mf++)
                #pragma unroll
                for (int nf = 0; nf < 4; nf++)
                    mma_bf16(acc[mf][nf], afr[mf], bfr[nf][0], bfr[nf][1]);
        }

        // mbarrier.arrive has release semantics: orders the LDSMs above
        if (lane == 0) MBAR_ARRIVE(sb + cst * 16 + 8);
        cst++; if (cst == NSTG) { cst = 0; cph ^= 1; }
    }

    #pragma unroll
    for (int mf = 0; mf < 4; mf++) {
        int grow = brow + warpM + mf * 16 + (lane >> 2);
        #pragma unroll
        for (int nf = 0; nf < 4; nf++) {
            int gcol = bcol + warpN + nf * 8 + (lane & 3) * 2;
            float bx = bias[gcol], by = bias[gcol + 1];
            float* d = acc[mf][nf];
            float2 v0 = {d[0] + bx, d[1] + by};
            float2 v1 = {d[2] + bx, d[3] + by};
            *(float2*)&C[(size_t)grow * Ndim + gcol] = v0;
            *(float2*)&C[(size_t)(grow + 8) * Ndim + gcol] = v1;
        }
    }
}

// ============ RoPE + hi/lo split ============
__global__ __launch_bounds__(256) void rope_split_kernel()
{
    int idx = blockIdx.x * blockDim.x + threadIdx.x;
    int i = idx & 31;
    int s = (idx >> 5)  & (Sn - 1);
    int h = (idx >> 15) & (Hn - 1);
    int b =  idx >> 19;

    const float* row = g_qkv + (size_t)(b * Sn + s) * N1;
    int base = h * Dn;

    float inv = expf(-(logf(10000.f) / Dn) * (2.f * i));
    float ang = (float)s * inv;
    float sn, cs;
    sincosf(ang, &sn, &cs);

    float q1 = row[0*Cn + base + i];
    float q2 = row[0*Cn + base + i + 32];
    float k1 = row[1*Cn + base + i];
    float k2 = row[1*Cn + base + i + 32];
    float v1 = row[2*Cn + base + i];
    float v2 = row[2*Cn + base + i + 32];

    const float QS = 0.18033688011112042f;  // 0.125 * log2(e)

    float qa = (q1 * cs - q2 * sn) * QS;
    float qb = (q2 * cs + q1 * sn) * QS;
    float ka = k1 * cs - k2 * sn;
    float kb = k2 * cs + k1 * sn;

    size_t o = ((size_t)(b * Hn + h) * Sn + s) * Dn;
    __nv_bfloat16 hh, ll;
    split2(qa, hh, ll); g_qh[o + i] = hh;      g_ql[o + i] = ll;
    split2(qb, hh, ll); g_qh[o + i + 32] = hh; g_ql[o + i + 32] = ll;
    split2(ka, hh, ll); g_kh[o + i] = hh;      g_kl[o + i] = ll;
    split2(kb, hh, ll); g_kh[o + i + 32] = hh; g_kl[o + i + 32] = ll;
    split2(v1, hh, ll); g_vh[o + i] = hh;      g_vl[o + i] = ll;
    split2(v2, hh, ll); g_vh[o + i + 32] = hh; g_vl[o + i + 32] = ll;
}

// ============ HMMA flash attention ============
#define AT_ROWB 144
#define AT_TILE (128 * AT_ROWB)
#define AT_STAGE (4 * AT_TILE)
#define AT_SMEM (2 * AT_TILE + 2 * AT_STAGE)

__global__ __launch_bounds__(256, 1) void attn_mma()
{
    extern __shared__ char smraw[];
    const uint32_t sb = smem_u32(smraw);
    const int tid = threadIdx.x, wid = tid >> 5, lane = tid & 31;
    const int bh = blockIdx.y;
    const int q0 = blockIdx.x * 128;
    const size_t bhoff = (size_t)bh * Sn * Dn;

    const uint32_t qhi_s = sb;
    const uint32_t qlo_s = sb + AT_TILE;
    const uint32_t stage0 = sb + 2 * AT_TILE;

    {
        const __nv_bfloat16* Qh = g_qh + bhoff + (size_t)q0 * Dn;
        const __nv_bfloat16* Ql = g_ql + bhoff + (size_t)q0 * Dn;
        #pragma unroll
        for (int i = 0; i < 4; i++) {
            int slot = i * 256 + tid;
            int r = slot >> 3, c = slot & 7;
            uint32_t so = (uint32_t)(r * AT_ROWB + c * 16);
            cpa16(qhi_s + so, Qh + (size_t)r * Dn + c * 8);
            cpa16(qlo_s + so, Ql + (size_t)r * Dn + c * 8);
        }
    }
    auto load_kv = [&](int t, int buf) {
        uint32_t st = stage0 + buf * AT_STAGE;
        const __nv_bfloat16* Kh = g_kh + bhoff + (size_t)t * 128 * Dn;
        const __nv_bfloat16* Kl = g_kl + bhoff + (size_t)t * 128 * Dn;
        const __nv_bfloat16* Vh = g_vh + bhoff + (size_t)t * 128 * Dn;
        const __nv_bfloat16* Vl = g_vl + bhoff + (size_t)t * 128 * Dn;
        #pragma unroll
        for (int i = 0; i < 4; i++) {
            int slot = i * 256 + tid;
            int r = slot >> 3, c = slot & 7;
            uint32_t so = (uint32_t)(r * AT_ROWB + c * 16);
            size_t go = (size_t)r * Dn + c * 8;
            cpa16(st + so, Kh + go);
            cpa16(st + AT_TILE + so, Kl + go);
            cpa16(st + 2 * AT_TILE + so, Vh + go);
            cpa16(st + 3 * AT_TILE + so, Vl + go);
        }
        asm volatile("cp.async.commit_group;" ::: "memory");
    };
    load_kv(0, 0);

    asm volatile("cp.async.wait_group 0;" ::: "memory");
    __syncthreads();

    const int lm = lane & 15, lh = lane >> 4;
    uint32_t qh[4][4], ql[4][4];
    {
        uint32_t a = (uint32_t)((wid * 16 + lm) * AT_ROWB + lh * 16);
        #pragma unroll
        for (int ks = 0; ks < 4; ks++) {
            ldm4(qhi_s + a + ks * 32, qh[ks][0], qh[ks][1], qh[ks][2], qh[ks][3]);
            ldm4(qlo_s + a + ks * 32, ql[ks][0], ql[ks][1], ql[ks][2], ql[ks][3]);
        }
    }

    float o[8][4];
    #pragma unroll
    for (int i = 0; i < 8; i++)
        #pragma unroll
        for (int e = 0; e < 4; e++) o[i][e] = 0.f;
    float m0 = -1e30f, m1 = -1e30f, ps0 = 0.f, ps1 = 0.f;

    for (int t = 0; t < 8; t++) {
        if (t > 0) {
            asm volatile("cp.async.wait_group 0;" ::: "memory");
            __syncthreads();
        }
        if (t < 7) load_kv(t + 1, (t + 1) & 1);

        uint32_t st = stage0 + (t & 1) * AT_STAGE;
        uint32_t kh_s = st, kl_s = st + AT_TILE;
        uint32_t vh_s = st + 2 * AT_TILE, vl_s = st + 3 * AT_TILE;

        float sc[16][4];
        #pragma unroll
        for (int f = 0; f < 16; f++)
            #pragma unroll
            for (int e = 0; e < 4; e++) sc[f][e] = 0.f;

        uint32_t bbase = (uint32_t)(lm * AT_ROWB + lh * 16);
        #pragma unroll
        for (int nb = 0; nb < 8; nb++) {
            uint32_t ah = kh_s + bbase + nb * 16 * AT_ROWB;
            uint32_t al = kl_s + bbase + nb * 16 * AT_ROWB;
            #pragma unroll
            for (int ks = 0; ks < 4; ks++) {
                uint32_t h0, h1, h2, h3, l0, l1, l2, l3;
                ldm4(ah + ks * 32, h0, h1, h2, h3);
                ldm4(al + ks * 32, l0, l1, l2, l3);
                mma_bf16(sc[2 * nb],     qh[ks], h0, h2);
                mma_bf16(sc[2 * nb],     ql[ks], h0, h2);
                mma_bf16(sc[2 * nb],     qh[ks], l0, l2);
                mma_bf16(sc[2 * nb + 1], qh[ks], h1, h3);
                mma_bf16(sc[2 * nb + 1], ql[ks], h1, h3);
                mma_bf16(sc[2 * nb + 1], qh[ks], l1, l3);
            }
        }

        float mx0 = -1e30f, mx1 = -1e30f;
        #pragma unroll
        for (int f = 0; f < 16; f++) {
            mx0 = fmaxf(mx0, fmaxf(sc[f][0], sc[f][1]));
            mx1 = fmaxf(mx1, fmaxf(sc[f][2], sc[f][3]));
        }
        mx0 = fmaxf(mx0, __shfl_xor_sync(0xffffffffu, mx0, 1));
        mx0 = fmaxf(mx0, __shfl_xor_sync(0xffffffffu, mx0, 2));
        mx1 = fmaxf(mx1, __shfl_xor_sync(0xffffffffu, mx1, 1));
        mx1 = fmaxf(mx1, __shfl_xor_sync(0xffffffffu, mx1, 2));

        float mn0 = fmaxf(m0, mx0), mn1 = fmaxf(m1, mx1);
        float f0 = ex2(m0 - mn0), f1 = ex2(m1 - mn1);
        m0 = mn0; m1 = mn1;
        ps0 *= f0; ps1 *= f1;
        #pragma unroll
        for (int nf = 0; nf < 8; nf++) {
            o[nf][0] *= f0; o[nf][1] *= f0;
            o[nf][2] *= f1; o[nf][3] *= f1;
        }

        uint32_t pa_hi[8][4], pa_lo[8][4];
        #pragma unroll
        for (int t2 = 0; t2 < 8; t2++) {
            #pragma unroll
            for (int half = 0; half < 2; half++) {
                int f = 2 * t2 + half;
                float p0 = ex2(sc[f][0] - m0);
                float p1 = ex2(sc[f][1] - m0);
                float p2 = ex2(sc[f][2] - m1);
                float p3 = ex2(sc[f][3] - m1);
                ps0 += p0 + p1; ps1 += p2 + p3;
                __nv_bfloat16 h0, l0, h1, l1, h2, l2, h3, l3;
                split2(p0, h0, l0); split2(p1, h1, l1);
                split2(p2, h2, l2); split2(p3, h3, l3);
                pa_hi[t2][half * 2 + 0] = packbf(h0, h1);
                pa_hi[t2][half * 2 + 1] = packbf(h2, h3);
                pa_lo[t2][half * 2 + 0] = packbf(l0, l1);
                pa_lo[t2][half * 2 + 1] = packbf(l2, l3);
            }
        }

        #pragma unroll
        for (int t2 = 0; t2 < 8; t2++) {
            uint32_t vrow = (uint32_t)((t2 * 16 + lm) * AT_ROWB + lh * 16);
            #pragma unroll
            for (int dn = 0; dn < 4; dn++) {
                uint32_t h0, h1, h2, h3, l0, l1, l2, l3;
                ldm4t(vh_s + vrow + dn * 32, h0, h1, h2, h3);
                ldm4t(vl_s + vrow + dn * 32, l0, l1, l2, l3);
                mma_bf16(o[2 * dn],     pa_hi[t2], h0, h1);
                mma_bf16(o[2 * dn],     pa_lo[t2], h0, h1);
                mma_bf16(o[2 * dn],     pa_hi[t2], l0, l1);
                mma_bf16(o[2 * dn + 1], pa_hi[t2], h2, h3);
                mma_bf16(o[2 * dn + 1], pa_lo[t2], h2, h3);
                mma_bf16(o[2 * dn + 1], pa_hi[t2], l2, l3);
            }
        }
    }

    ps0 += __shfl_xor_sync(0xffffffffu, ps0, 1);
    ps0 += __shfl_xor_sync(0xffffffffu, ps0, 2);
    ps1 += __shfl_xor_sync(0xffffffffu, ps1, 1);
    ps1 += __shfl_xor_sync(0xffffffffu, ps1, 2);
    float inv0 = 1.f / ps0, inv1 = 1.f / ps1;

    const int bidx = bh >> 4, hidx = bh & 15;
    const int grow = bidx * Sn + q0 + wid * 16 + (lane >> 2);

    #pragma unroll
    for (int nf = 0; nf < 8; nf++) {
        int col = hidx * 64 + nf * 8 + (lane & 3) * 2;
        float v0 = o[nf][0] * inv0, v1 = o[nf][1] * inv0;
        float v2 = o[nf][2] * inv1, v3 = o[nf][3] * inv1;
        __nv_bfloat16 h0, l0, h1, l1, h2, l2, h3, l3;
        split2(v0, h0, l0); split2(v1, h1, l1);
        split2(v2, h2, l2); split2(v3, h3, l3);
        uint32_t hp0 = packbf(h0, h1), lp0 = packbf(l0, l1);
        uint32_t hp1 = packbf(h2, h3), lp1 = packbf(l2, l3);
        size_t r0 = (size_t)grow * KP + col;
        size_t r1 = (size_t)(grow + 8) * KP + col;
        *(uint32_t*)&g_A3[r0]        = hp0;
        *(uint32_t*)&g_A3[r0 + 1024] = lp0;
        *(uint32_t*)&g_A3[r0 + 2048] = hp0;
        *(uint32_t*)&g_A3[r1]        = hp1;
        *(uint32_t*)&g_A3[r1 + 1024] = lp1;
        *(uint32_t*)&g_A3[r1 + 2048] = hp1;
    }
}

// ============ launch ============
extern "C" void kernel_launch(void* const* d_in, const int* in_sizes, int n_in,
                              void* d_out, int out_size)
{
    const float* x      = (const float*)d_in[0];
    const float* W_qkv  = (const float*)d_in[1];
    const float* b_qkv  = (const float*)d_in[2];
    const float* W_proj = (const float*)d_in[3];
    const float* b_proj = (const float*)d_in[4];
    float* out = (float*)d_out;

    cudaFuncSetAttribute(gemm_mma, cudaFuncAttributeMaxDynamicSharedMemorySize, GM_SMEM);
    cudaFuncSetAttribute(attn_mma, cudaFuncAttributeMaxDynamicSharedMemorySize, AT_SMEM);

    float* p_qkv;
    __nv_bfloat16 *p_A3, *p_B3, *p_B3p;
    cudaGetSymbolAddress((void**)&p_qkv, g_qkv);
    cudaGetSymbolAddress((void**)&p_A3, g_A3);
    cudaGetSymbolAddress((void**)&p_B3, g_B3);
    cudaGetSymbolAddress((void**)&p_B3p, g_B3p);

    // launches ordered so the QKV GEMM is #4 (ncu captures launch 4)
    conv_A<<<(Mn * Cn) / 256, 256>>>(x, p_A3, Cn);                        // 1
    { dim3 g(Cn / 32, N1 / 32); conv_B<<<g, 256>>>(W_qkv, p_B3, Cn, N1); }   // 2
    { dim3 g(Cn / 32, Cn / 32); conv_B<<<g, 256>>>(W_proj, p_B3p, Cn, Cn); } // 3
    { dim3 g(N1 / 128, Mn / 128);
      gemm_mma<<<g, 288, GM_SMEM>>>(p_A3, p_B3, b_qkv, p_qkv, N1, KP); }     // 4 (profiled)
    rope_split_kernel<<<(Bn * Hn * Sn * 32) / 256, 256>>>();                 // 5
    { dim3 g(Sn / 128, Bn * Hn); attn_mma<<<g, 256, AT_SMEM>>>(); }          // 6
    { dim3 g(Cn / 128, Mn / 128);
      gemm_mma<<<g, 288, GM_SMEM>>>(p_A3, p_B3p, b_proj, out, Cn, KP); }     // 7
}

// round 9
// speedup vs baseline: 1.0090x; 1.0013x over previous
#include <cuda_runtime.h>
#include <cuda_bf16.h>
#include <math.h>
#include <cstdint>

#define Bn 8
#define Sn 1024
#define Cn 1024
#define Hn 16
#define Dn 64
#define Mn (Bn*Sn)
#define N1 (3*Cn)
#define KP (3*Cn)

__device__ float g_qkv[(size_t)Mn * N1];
__device__ __nv_bfloat16 g_qh[(size_t)Bn*Hn*Sn*Dn];
__device__ __nv_bfloat16 g_ql[(size_t)Bn*Hn*Sn*Dn];
__device__ __nv_bfloat16 g_kh[(size_t)Bn*Hn*Sn*Dn];
__device__ __nv_bfloat16 g_kl[(size_t)Bn*Hn*Sn*Dn];
__device__ __nv_bfloat16 g_vh[(size_t)Bn*Hn*Sn*Dn];
__device__ __nv_bfloat16 g_vl[(size_t)Bn*Hn*Sn*Dn];
__device__ __nv_bfloat16 g_A3[(size_t)Mn * KP];
__device__ __nv_bfloat16 g_B3[(size_t)N1 * KP];     // qkv weights split
__device__ __nv_bfloat16 g_B3p[(size_t)Cn * KP];    // proj weights split

__device__ __forceinline__ uint32_t smem_u32(const void* p) {
    uint32_t a;
    asm("{ .reg .u64 t; cvta.to.shared.u64 t, %1; cvt.u32.u64 %0, t; }" : "=r"(a) : "l"(p));
    return a;
}
__device__ __forceinline__ void cpa16(uint32_t s, const void* g) {
    asm volatile("cp.async.cg.shared.global [%0], [%1], 16;" :: "r"(s), "l"(g));
}
__device__ __forceinline__ void ldm4(uint32_t a, uint32_t& r0, uint32_t& r1, uint32_t& r2, uint32_t& r3) {
    asm volatile("ldmatrix.sync.aligned.m8n8.x4.shared.b16 {%0,%1,%2,%3}, [%4];"
                 : "=r"(r0), "=r"(r1), "=r"(r2), "=r"(r3) : "r"(a));
}
__device__ __forceinline__ void ldm4t(uint32_t a, uint32_t& r0, uint32_t& r1, uint32_t& r2, uint32_t& r3) {
    asm volatile("ldmatrix.sync.aligned.m8n8.x4.trans.shared.b16 {%0,%1,%2,%3}, [%4];"
                 : "=r"(r0), "=r"(r1), "=r"(r2), "=r"(r3) : "r"(a));
}
__device__ __forceinline__ void mma_bf16(float* d, const uint32_t* a, uint32_t b0, uint32_t b1) {
    asm volatile("mma.sync.aligned.m16n8k16.row.col.f32.bf16.bf16.f32 "
        "{%0,%1,%2,%3}, {%4,%5,%6,%7}, {%8,%9}, {%0,%1,%2,%3};"
        : "+f"(d[0]), "+f"(d[1]), "+f"(d[2]), "+f"(d[3])
        : "r"(a[0]), "r"(a[1]), "r"(a[2]), "r"(a[3]), "r"(b0), "r"(b1));
}
__device__ __forceinline__ float ex2(float x) { float r; asm("ex2.approx.f32 %0, %1;" : "=f"(r) : "f"(x)); return r; }
__device__ __forceinline__ void split2(float v, __nv_bfloat16& h, __nv_bfloat16& l) {
    h = __float2bfloat16(v);
    l = __float2bfloat16(v - __bfloat162float(h));
}
__device__ __forceinline__ uint32_t packbf(__nv_bfloat16 a, __nv_bfloat16 b) {
    __nv_bfloat162 t(a, b); return *(uint32_t*)&t;
}

#define MBAR_INIT(a, n) asm volatile("mbarrier.init.shared.b64 [%0], %1;" :: "r"(a), "r"(n) : "memory")
#define MBAR_ARRIVE(a)  asm volatile("mbarrier.arrive.shared.b64 _, [%0];" :: "r"(a) : "memory")
// .noinc: consume a pre-initialized expected arrival (default form deadlocks)
#define MBAR_ARRIVE_CP(a) asm volatile("cp.async.mbarrier.arrive.noinc.shared::cta.b64 [%0];" :: "r"(a) : "memory")
#define MBAR_WAIT(mb, ph) do { \
    uint32_t _m = (mb); uint32_t _p = (ph); uint32_t _d; \
    asm volatile("{ .reg .pred p; mbarrier.try_wait.parity.acquire.cta.shared::cta.b64 p, [%1], %2;" \
                 " selp.b32 %0,1,0,p; }" : "=r"(_d) : "r"(_m), "r"(_p) : "memory"); \
    if (!_d) { \
        asm volatile("{ .reg .pred P1; WL_%=:" \
                     " mbarrier.try_wait.parity.acquire.cta.shared::cta.b64 P1, [%0], %1, 0x989680;" \
                     " @P1 bra.uni WD_%=; bra.uni WL_%=; WD_%=: }" :: "r"(_m), "r"(_p) : "memory"); \
    } \
} while (0)

// ============ split conversions ============
__global__ __launch_bounds__(256) void conv_A(const float* __restrict__ A,
                                              __nv_bfloat16* __restrict__ A3, int Kdim)
{
    int idx = blockIdx.x * 256 + threadIdx.x;
    int r = idx / Kdim, k = idx - r * Kdim;
    float v = A[idx];
    __nv_bfloat16 hi, lo; split2(v, hi, lo);
    size_t base = (size_t)r * (3 * Kdim);
    A3[base + k] = hi; A3[base + Kdim + k] = lo; A3[base + 2 * Kdim + k] = hi;
}

__global__ __launch_bounds__(256) void conv_B(const float* __restrict__ W,
                                              __nv_bfloat16* __restrict__ B3,
                                              int Kdim, int Ndim)
{
    __shared__ float t[32][33];
    int k0 = blockIdx.x * 32, n0 = blockIdx.y * 32;
    int tx = threadIdx.x & 31, ty = threadIdx.x >> 5;
    #pragma unroll
    for (int i = 0; i < 4; i++)
        t[ty + i * 8][tx] = W[(size_t)(k0 + ty + i * 8) * Ndim + n0 + tx];
    __syncthreads();
    #pragma unroll
    for (int i = 0; i < 4; i++) {
        int n = ty + i * 8;
        float v = t[tx][n];
        __nv_bfloat16 hi, lo; split2(v, hi, lo);
        size_t base = (size_t)(n0 + n) * (3 * Kdim);
        B3[base + k0 + tx] = hi;
        B3[base + Kdim + k0 + tx] = hi;
        B3[base + 2 * Kdim + k0 + tx] = lo;
    }
}

// ============ warp-specialized HMMA GEMM ============
// 544 thr: warps 0-15 consumers (4x4 grid of 32x32 tiles), warp 16 producer.
// 5 stages, mbarrier full/empty, no CTA syncs in mainloop.
#define KT 64
#define ROWB 144
#define TILEB (128 * ROWB)
#define NSTG 5
#define GM_SMEM (1024 + NSTG * 2 * TILEB)   // 185344 B

__global__ __launch_bounds__(544, 1) void gemm_mma(
    const __nv_bfloat16* __restrict__ A, const __nv_bfloat16* __restrict__ B,
    const float* __restrict__ bias, float* __restrict__ C,
    int Ndim, int Kp)
{
    extern __shared__ char smraw[];
    const uint32_t sb = smem_u32(smraw);
    const uint32_t dat = sb + 1024;
    const int tid = threadIdx.x;
    const int wid = tid >> 5, lane = tid & 31;
    const int brow = blockIdx.y * 128, bcol = blockIdx.x * 128;
    const int NT = Kp / KT;

    if (tid == 0) {
        #pragma unroll
        for (int s = 0; s < NSTG; s++) {
            MBAR_INIT(sb + s * 16, 32);      // full: 32 producer-lane cp arrivals
            MBAR_INIT(sb + s * 16 + 8, 16);  // empty: 16 consumer warps
        }
    }
    __syncthreads();

    if (wid == 16) {
        // -------- producer --------
        int pst = 0, pph = 1;
        for (int kt = 0; kt < NT; kt++) {
            MBAR_WAIT(sb + pst * 16 + 8, pph);
            const __nv_bfloat16* Ag = A + (size_t)brow * Kp + kt * KT;
            const __nv_bfloat16* Bg = B + (size_t)bcol * Kp + kt * KT;
            uint32_t ab = dat + pst * (2 * TILEB);
            #pragma unroll
            for (int i = 0; i < 32; i++) {
                int chunk = lane + i * 32;          // 0..1023
                int r = chunk >> 3, c = chunk & 7;
                uint32_t so = (uint32_t)(r * ROWB + c * 16);
                cpa16(ab + so, Ag + (size_t)r * Kp + c * 8);
                cpa16(ab + TILEB + so, Bg + (size_t)r * Kp + c * 8);
            }
            MBAR_ARRIVE_CP(sb + pst * 16);
            pst++; if (pst == NSTG) { pst = 0; pph ^= 1; }
        }
        return;
    }

    // -------- consumers: 4x4 warp grid, 32x32 tile each --------
    const int warpM = (wid >> 2) * 32;
    const int warpN = (wid & 3) * 32;
    const int lm = lane & 15, lh = lane >> 4;

    float acc[2][4][4];
    #pragma unroll
    for (int i = 0; i < 2; i++)
        #pragma unroll
        for (int j = 0; j < 4; j++)
            #pragma unroll
            for (int e = 0; e < 4; e++) acc[i][j][e] = 0.f;

    int cst = 0, cph = 0;
    for (int kt = 0; kt < NT; kt++) {
        MBAR_WAIT(sb + cst * 16, cph);

        uint32_t ab = dat + cst * (2 * TILEB);
        uint32_t bb = ab + TILEB;
        uint32_t aAddr = ab + (uint32_t)((warpM + lm) * ROWB + lh * 16);
        uint32_t bAddr = bb + (uint32_t)((warpN + lm) * ROWB + lh * 16);

        #pragma unroll
        for (int ks = 0; ks < 4; ks++) {
            uint32_t afr[2][4];
            #pragma unroll
            for (int mf = 0; mf < 2; mf++)
                ldm4(aAddr + mf * 16 * ROWB + ks * 32,
                     afr[mf][0], afr[mf][1], afr[mf][2], afr[mf][3]);
            uint32_t bfr[4][2];
            #pragma unroll
            for (int nb = 0; nb < 2; nb++) {
                uint32_t r0, r1, r2, r3;
                ldm4(bAddr + nb * 16 * ROWB + ks * 32, r0, r1, r2, r3);
                bfr[nb * 2 + 0][0] = r0; bfr[nb * 2 + 0][1] = r2;
                bfr[nb * 2 + 1][0] = r1; bfr[nb * 2 + 1][1] = r3;
            }
            #pragma unroll
            for (int mf = 0; mf < 2; mf++)
                #pragma unroll
                for (int nf = 0; nf < 4; nf++)
                    mma_bf16(acc[mf][nf], afr[mf], bfr[nf][0], bfr[nf][1]);
        }

        if (lane == 0) MBAR_ARRIVE(sb + cst * 16 + 8);
        cst++; if (cst == NSTG) { cst = 0; cph ^= 1; }
    }

    #pragma unroll
    for (int mf = 0; mf < 2; mf++) {
        int grow = brow + warpM + mf * 16 + (lane >> 2);
        #pragma unroll
        for (int nf = 0; nf < 4; nf++) {
            int gcol = bcol + warpN + nf * 8 + (lane & 3) * 2;
            float bx = bias[gcol], by = bias[gcol + 1];
            float* d = acc[mf][nf];
            float2 v0 = {d[0] + bx, d[1] + by};
            float2 v1 = {d[2] + bx, d[3] + by};
            *(float2*)&C[(size_t)grow * Ndim + gcol] = v0;
            *(float2*)&C[(size_t)(grow + 8) * Ndim + gcol] = v1;
        }
    }
}

// ============ RoPE + hi/lo split ============
__global__ __launch_bounds__(256) void rope_split_kernel()
{
    int idx = blockIdx.x * blockDim.x + threadIdx.x;
    int i = idx & 31;
    int s = (idx >> 5)  & (Sn - 1);
    int h = (idx >> 15) & (Hn - 1);
    int b =  idx >> 19;

    const float* row = g_qkv + (size_t)(b * Sn + s) * N1;
    int base = h * Dn;

    float inv = expf(-(logf(10000.f) / Dn) * (2.f * i));
    float ang = (float)s * inv;
    float sn, cs;
    sincosf(ang, &sn, &cs);

    float q1 = row[0*Cn + base + i];
    float q2 = row[0*Cn + base + i + 32];
    float k1 = row[1*Cn + base + i];
    float k2 = row[1*Cn + base + i + 32];
    float v1 = row[2*Cn + base + i];
    float v2 = row[2*Cn + base + i + 32];

    const float QS = 0.18033688011112042f;  // 0.125 * log2(e)

    float qa = (q1 * cs - q2 * sn) * QS;
    float qb = (q2 * cs + q1 * sn) * QS;
    float ka = k1 * cs - k2 * sn;
    float kb = k2 * cs + k1 * sn;

    size_t o = ((size_t)(b * Hn + h) * Sn + s) * Dn;
    __nv_bfloat16 hh, ll;
    split2(qa, hh, ll); g_qh[o + i] = hh;      g_ql[o + i] = ll;
    split2(qb, hh, ll); g_qh[o + i + 32] = hh; g_ql[o + i + 32] = ll;
    split2(ka, hh, ll); g_kh[o + i] = hh;      g_kl[o + i] = ll;
    split2(kb, hh, ll); g_kh[o + i + 32] = hh; g_kl[o + i + 32] = ll;
    split2(v1, hh, ll); g_vh[o + i] = hh;      g_vl[o + i] = ll;
    split2(v2, hh, ll); g_vh[o + i + 32] = hh; g_vl[o + i + 32] = ll;
}

// ============ HMMA flash attention ============
#define AT_ROWB 144
#define AT_TILE (128 * AT_ROWB)
#define AT_STAGE (4 * AT_TILE)
#define AT_SMEM (2 * AT_TILE + 2 * AT_STAGE)

__global__ __launch_bounds__(256, 1) void attn_mma()
{
    extern __shared__ char smraw[];
    const uint32_t sb = smem_u32(smraw);
    const int tid = threadIdx.x, wid = tid >> 5, lane = tid & 31;
    const int bh = blockIdx.y;
    const int q0 = blockIdx.x * 128;
    const size_t bhoff = (size_t)bh * Sn * Dn;

    const uint32_t qhi_s = sb;
    const uint32_t qlo_s = sb + AT_TILE;
    const uint32_t stage0 = sb + 2 * AT_TILE;

    {
        const __nv_bfloat16* Qh = g_qh + bhoff + (size_t)q0 * Dn;
        const __nv_bfloat16* Ql = g_ql + bhoff + (size_t)q0 * Dn;
        #pragma unroll
        for (int i = 0; i < 4; i++) {
            int slot = i * 256 + tid;
            int r = slot >> 3, c = slot & 7;
            uint32_t so = (uint32_t)(r * AT_ROWB + c * 16);
            cpa16(qhi_s + so, Qh + (size_t)r * Dn + c * 8);
            cpa16(qlo_s + so, Ql + (size_t)r * Dn + c * 8);
        }
    }
    auto load_kv = [&](int t, int buf) {
        uint32_t st = stage0 + buf * AT_STAGE;
        const __nv_bfloat16* Kh = g_kh + bhoff + (size_t)t * 128 * Dn;
        const __nv_bfloat16* Kl = g_kl + bhoff + (size_t)t * 128 * Dn;
        const __nv_bfloat16* Vh = g_vh + bhoff + (size_t)t * 128 * Dn;
        const __nv_bfloat16* Vl = g_vl + bhoff + (size_t)t * 128 * Dn;
        #pragma unroll
        for (int i = 0; i < 4; i++) {
            int slot = i * 256 + tid;
            int r = slot >> 3, c = slot & 7;
            uint32_t so = (uint32_t)(r * AT_ROWB + c * 16);
            size_t go = (size_t)r * Dn + c * 8;
            cpa16(st + so, Kh + go);
            cpa16(st + AT_TILE + so, Kl + go);
            cpa16(st + 2 * AT_TILE + so, Vh + go);
            cpa16(st + 3 * AT_TILE + so, Vl + go);
        }
        asm volatile("cp.async.commit_group;" ::: "memory");
    };
    load_kv(0, 0);

    asm volatile("cp.async.wait_group 0;" ::: "memory");
    __syncthreads();

    const int lm = lane & 15, lh = lane >> 4;
    uint32_t qh[4][4], ql[4][4];
    {
        uint32_t a = (uint32_t)((wid * 16 + lm) * AT_ROWB + lh * 16);
        #pragma unroll
        for (int ks = 0; ks < 4; ks++) {
            ldm4(qhi_s + a + ks * 32, qh[ks][0], qh[ks][1], qh[ks][2], qh[ks][3]);
            ldm4(qlo_s + a + ks * 32, ql[ks][0], ql[ks][1], ql[ks][2], ql[ks][3]);
        }
    }

    float o[8][4];
    #pragma unroll
    for (int i = 0; i < 8; i++)
        #pragma unroll
        for (int e = 0; e < 4; e++) o[i][e] = 0.f;
    float m0 = -1e30f, m1 = -1e30f, ps0 = 0.f, ps1 = 0.f;

    for (int t = 0; t < 8; t++) {
        if (t > 0) {
            asm volatile("cp.async.wait_group 0;" ::: "memory");
            __syncthreads();
        }
        if (t < 7) load_kv(t + 1, (t + 1) & 1);

        uint32_t st = stage0 + (t & 1) * AT_STAGE;
        uint32_t kh_s = st, kl_s = st + AT_TILE;
        uint32_t vh_s = st + 2 * AT_TILE, vl_s = st + 3 * AT_TILE;

        float sc[16][4];
        #pragma unroll
        for (int f = 0; f < 16; f++)
            #pragma unroll
            for (int e = 0; e < 4; e++) sc[f][e] = 0.f;

        uint32_t bbase = (uint32_t)(lm * AT_ROWB + lh * 16);
        #pragma unroll
        for (int nb = 0; nb < 8; nb++) {
            uint32_t ah = kh_s + bbase + nb * 16 * AT_ROWB;
            uint32_t al = kl_s + bbase + nb * 16 * AT_ROWB;
            #pragma unroll
            for (int ks = 0; ks < 4; ks++) {
                uint32_t h0, h1, h2, h3, l0, l1, l2, l3;
                ldm4(ah + ks * 32, h0, h1, h2, h3);
                ldm4(al + ks * 32, l0, l1, l2, l3);
                mma_bf16(sc[2 * nb],     qh[ks], h0, h2);
                mma_bf16(sc[2 * nb],     ql[ks], h0, h2);
                mma_bf16(sc[2 * nb],     qh[ks], l0, l2);
                mma_bf16(sc[2 * nb + 1], qh[ks], h1, h3);
                mma_bf16(sc[2 * nb + 1], ql[ks], h1, h3);
                mma_bf16(sc[2 * nb + 1], qh[ks], l1, l3);
            }
        }

        float mx0 = -1e30f, mx1 = -1e30f;
        #pragma unroll
        for (int f = 0; f < 16; f++) {
            mx0 = fmaxf(mx0, fmaxf(sc[f][0], sc[f][1]));
            mx1 = fmaxf(mx1, fmaxf(sc[f][2], sc[f][3]));
        }
        mx0 = fmaxf(mx0, __shfl_xor_sync(0xffffffffu, mx0, 1));
        mx0 = fmaxf(mx0, __shfl_xor_sync(0xffffffffu, mx0, 2));
        mx1 = fmaxf(mx1, __shfl_xor_sync(0xffffffffu, mx1, 1));
        mx1 = fmaxf(mx1, __shfl_xor_sync(0xffffffffu, mx1, 2));

        float mn0 = fmaxf(m0, mx0), mn1 = fmaxf(m1, mx1);
        float f0 = ex2(m0 - mn0), f1 = ex2(m1 - mn1);
        m0 = mn0; m1 = mn1;
        ps0 *= f0; ps1 *= f1;
        #pragma unroll
        for (int nf = 0; nf < 8; nf++) {
            o[nf][0] *= f0; o[nf][1] *= f0;
            o[nf][2] *= f1; o[nf][3] *= f1;
        }

        uint32_t pa_hi[8][4], pa_lo[8][4];
        #pragma unroll
        for (int t2 = 0; t2 < 8; t2++) {
            #pragma unroll
            for (int half = 0; half < 2; half++) {
                int f = 2 * t2 + half;
                float p0 = ex2(sc[f][0] - m0);
                float p1 = ex2(sc[f][1] - m0);
                float p2 = ex2(sc[f][2] - m1);
                float p3 = ex2(sc[f][3] - m1);
                ps0 += p0 + p1; ps1 += p2 + p3;
                __nv_bfloat16 h0, l0, h1, l1, h2, l2, h3, l3;
                split2(p0, h0, l0); split2(p1, h1, l1);
                split2(p2, h2, l2); split2(p3, h3, l3);
                pa_hi[t2][half * 2 + 0] = packbf(h0, h1);
                pa_hi[t2][half * 2 + 1] = packbf(h2, h3);
                pa_lo[t2][half * 2 + 0] = packbf(l0, l1);
                pa_lo[t2][half * 2 + 1] = packbf(l2, l3);
            }
        }

        #pragma unroll
        for (int t2 = 0; t2 < 8; t2++) {
            uint32_t vrow = (uint32_t)((t2 * 16 + lm) * AT_ROWB + lh * 16);
            #pragma unroll
            for (int dn = 0; dn < 4; dn++) {
                uint32_t h0, h1, h2, h3, l0, l1, l2, l3;
                ldm4t(vh_s + vrow + dn * 32, h0, h1, h2, h3);
                ldm4t(vl_s + vrow + dn * 32, l0, l1, l2, l3);
                mma_bf16(o[2 * dn],     pa_hi[t2], h0, h1);
                mma_bf16(o[2 * dn],     pa_lo[t2], h0, h1);
                mma_bf16(o[2 * dn],     pa_hi[t2], l0, l1);
                mma_bf16(o[2 * dn + 1], pa_hi[t2], h2, h3);
                mma_bf16(o[2 * dn + 1], pa_lo[t2], h2, h3);
                mma_bf16(o[2 * dn + 1], pa_hi[t2], l2, l3);
            }
        }
    }

    ps0 += __shfl_xor_sync(0xffffffffu, ps0, 1);
    ps0 += __shfl_xor_sync(0xffffffffu, ps0, 2);
    ps1 += __shfl_xor_sync(0xffffffffu, ps1, 1);
    ps1 += __shfl_xor_sync(0xffffffffu, ps1, 2);
    float inv0 = 1.f / ps0, inv1 = 1.f / ps1;

    const int bidx = bh >> 4, hidx = bh & 15;
    const int grow = bidx * Sn + q0 + wid * 16 + (lane >> 2);

    #pragma unroll
    for (int nf = 0; nf < 8; nf++) {
        int col = hidx * 64 + nf * 8 + (lane & 3) * 2;
        float v0 = o[nf][0] * inv0, v1 = o[nf][1] * inv0;
        float v2 = o[nf][2] * inv1, v3 = o[nf][3] * inv1;
        __nv_bfloat16 h0, l0, h1, l1, h2, l2, h3, l3;
        split2(v0, h0, l0); split2(v1, h1, l1);
        split2(v2, h2, l2); split2(v3, h3, l3);
        uint32_t hp0 = packbf(h0, h1), lp0 = packbf(l0, l1);
        uint32_t hp1 = packbf(h2, h3), lp1 = packbf(l2, l3);
        size_t r0 = (size_t)grow * KP + col;
        size_t r1 = (size_t)(grow + 8) * KP + col;
        *(uint32_t*)&g_A3[r0]        = hp0;
        *(uint32_t*)&g_A3[r0 + 1024] = lp0;
        *(uint32_t*)&g_A3[r0 + 2048] = hp0;
        *(uint32_t*)&g_A3[r1]        = hp1;
        *(uint32_t*)&g_A3[r1 + 1024] = lp1;
        *(uint32_t*)&g_A3[r1 + 2048] = hp1;
    }
}

// ============ launch ============
extern "C" void kernel_launch(void* const* d_in, const int* in_sizes, int n_in,
                              void* d_out, int out_size)
{
    const float* x      = (const float*)d_in[0];
    const float* W_qkv  = (const float*)d_in[1];
    const float* b_qkv  = (const float*)d_in[2];
    const float* W_proj = (const float*)d_in[3];
    const float* b_proj = (const float*)d_in[4];
    float* out = (float*)d_out;

    cudaFuncSetAttribute(gemm_mma, cudaFuncAttributeMaxDynamicSharedMemorySize, GM_SMEM);
    cudaFuncSetAttribute(attn_mma, cudaFuncAttributeMaxDynamicSharedMemorySize, AT_SMEM);

    float* p_qkv;
    __nv_bfloat16 *p_A3, *p_B3, *p_B3p;
    cudaGetSymbolAddress((void**)&p_qkv, g_qkv);
    cudaGetSymbolAddress((void**)&p_A3, g_A3);
    cudaGetSymbolAddress((void**)&p_B3, g_B3);
    cudaGetSymbolAddress((void**)&p_B3p, g_B3p);

    // launches ordered so the QKV GEMM is #4 (ncu captures launch 4)
    conv_A<<<(Mn * Cn) / 256, 256>>>(x, p_A3, Cn);                        // 1
    { dim3 g(Cn / 32, N1 / 32); conv_B<<<g, 256>>>(W_qkv, p_B3, Cn, N1); }   // 2
    { dim3 g(Cn / 32, Cn / 32); conv_B<<<g, 256>>>(W_proj, p_B3p, Cn, Cn); } // 3
    { dim3 g(N1 / 128, Mn / 128);
      gemm_mma<<<g, 544, GM_SMEM>>>(p_A3, p_B3, b_qkv, p_qkv, N1, KP); }     // 4 (profiled)
    rope_split_kernel<<<(Bn * Hn * Sn * 32) / 256, 256>>>();                 // 5
    { dim3 g(Sn / 128, Bn * Hn); attn_mma<<<g, 256, AT_SMEM>>>(); }          // 6
    { dim3 g(Cn / 128, Mn / 128);
      gemm_mma<<<g, 544, GM_SMEM>>>(p_A3, p_B3p, b_proj, out, Cn, KP); }     // 7
}

// round 10
// speedup vs baseline: 1.4537x; 1.4407x over previous
#include <cuda_runtime.h>
#include <cuda_fp16.h>
#include <math.h>
#include <cstdint>

#define Bn 8
#define Sn 1024
#define Cn 1024
#define Hn 16
#define Dn 64
#define Mn (Bn*Sn)
#define N1 (3*Cn)
#define KP (2*Cn)          // 2-product split: K' = 2K

__device__ float g_qkv[(size_t)Mn * N1];
__device__ __half g_qh[(size_t)Bn*Hn*Sn*Dn];
__device__ __half g_ql[(size_t)Bn*Hn*Sn*Dn];
__device__ __half g_kh[(size_t)Bn*Hn*Sn*Dn];   // K rounded once (no lo part)
__device__ __half g_vh[(size_t)Bn*Hn*Sn*Dn];   // V rounded once
__device__ __half g_A2[(size_t)Mn * KP];
__device__ __half g_B2[(size_t)N1 * KP];       // qkv weights split
__device__ __half g_B2p[(size_t)Cn * KP];      // proj weights split

__device__ __forceinline__ uint32_t smem_u32(const void* p) {
    uint32_t a;
    asm("{ .reg .u64 t; cvta.to.shared.u64 t, %1; cvt.u32.u64 %0, t; }" : "=r"(a) : "l"(p));
    return a;
}
__device__ __forceinline__ void cpa16(uint32_t s, const void* g) {
    asm volatile("cp.async.cg.shared.global [%0], [%1], 16;" :: "r"(s), "l"(g));
}
__device__ __forceinline__ void ldm4(uint32_t a, uint32_t& r0, uint32_t& r1, uint32_t& r2, uint32_t& r3) {
    asm volatile("ldmatrix.sync.aligned.m8n8.x4.shared.b16 {%0,%1,%2,%3}, [%4];"
                 : "=r"(r0), "=r"(r1), "=r"(r2), "=r"(r3) : "r"(a));
}
__device__ __forceinline__ void ldm4t(uint32_t a, uint32_t& r0, uint32_t& r1, uint32_t& r2, uint32_t& r3) {
    asm volatile("ldmatrix.sync.aligned.m8n8.x4.trans.shared.b16 {%0,%1,%2,%3}, [%4];"
                 : "=r"(r0), "=r"(r1), "=r"(r2), "=r"(r3) : "r"(a));
}
__device__ __forceinline__ void mma_f16(float* d, const uint32_t* a, uint32_t b0, uint32_t b1) {
    asm volatile("mma.sync.aligned.m16n8k16.row.col.f32.f16.f16.f32 "
        "{%0,%1,%2,%3}, {%4,%5,%6,%7}, {%8,%9}, {%0,%1,%2,%3};"
        : "+f"(d[0]), "+f"(d[1]), "+f"(d[2]), "+f"(d[3])
        : "r"(a[0]), "r"(a[1]), "r"(a[2]), "r"(a[3]), "r"(b0), "r"(b1));
}
__device__ __forceinline__ float ex2(float x) { float r; asm("ex2.approx.f32 %0, %1;" : "=f"(r) : "f"(x)); return r; }
__device__ __forceinline__ void split2h(float v, __half& h, __half& l) {
    h = __float2half_rn(v);
    l = __float2half_rn(v - __half2float(h));
}
__device__ __forceinline__ uint32_t packh(__half a, __half b) {
    __half2 t(a, b); return *(uint32_t*)&t;
}

#define MBAR_INIT(a, n) asm volatile("mbarrier.init.shared.b64 [%0], %1;" :: "r"(a), "r"(n) : "memory")
#define MBAR_ARRIVE(a)  asm volatile("mbarrier.arrive.shared.b64 _, [%0];" :: "r"(a) : "memory")
// .noinc: consume a pre-initialized expected arrival (default form deadlocks)
#define MBAR_ARRIVE_CP(a) asm volatile("cp.async.mbarrier.arrive.noinc.shared::cta.b64 [%0];" :: "r"(a) : "memory")
#define MBAR_WAIT(mb, ph) do { \
    uint32_t _m = (mb); uint32_t _p = (ph); uint32_t _d; \
    asm volatile("{ .reg .pred p; mbarrier.try_wait.parity.acquire.cta.shared::cta.b64 p, [%1], %2;" \
                 " selp.b32 %0,1,0,p; }" : "=r"(_d) : "r"(_m), "r"(_p) : "memory"); \
    if (!_d) { \
        asm volatile("{ .reg .pred P1; WL_%=:" \
                     " mbarrier.try_wait.parity.acquire.cta.shared::cta.b64 P1, [%0], %1, 0x989680;" \
                     " @P1 bra.uni WD_%=; bra.uni WL_%=; WD_%=: }" :: "r"(_m), "r"(_p) : "memory"); \
    } \
} while (0)

// ============ split conversions: A2 = [ah | al], B2 = [bh | bh] ============
__global__ __launch_bounds__(256) void conv_A(const float* __restrict__ A,
                                              __half* __restrict__ A2, int Kdim)
{
    int idx = blockIdx.x * 256 + threadIdx.x;
    int r = idx / Kdim, k = idx - r * Kdim;
    float v = A[idx];
    __half hi, lo; split2h(v, hi, lo);
    size_t base = (size_t)r * (2 * Kdim);
    A2[base + k] = hi; A2[base + Kdim + k] = lo;
}

__global__ __launch_bounds__(256) void conv_B(const float* __restrict__ W,
                                              __half* __restrict__ B2,
                                              int Kdim, int Ndim)
{
    __shared__ float t[32][33];
    int k0 = blockIdx.x * 32, n0 = blockIdx.y * 32;
    int tx = threadIdx.x & 31, ty = threadIdx.x >> 5;
    #pragma unroll
    for (int i = 0; i < 4; i++)
        t[ty + i * 8][tx] = W[(size_t)(k0 + ty + i * 8) * Ndim + n0 + tx];
    __syncthreads();
    #pragma unroll
    for (int i = 0; i < 4; i++) {
        int n = ty + i * 8;
        float v = t[tx][n];
        __half hi = __float2half_rn(v);
        size_t base = (size_t)(n0 + n) * (2 * Kdim);
        B2[base + k0 + tx] = hi;
        B2[base + Kdim + k0 + tx] = hi;   // duplicated: dot = (ah+al)*bh
    }
}

// ============ warp-specialized HMMA GEMM (fp16) ============
// 544 thr: warps 0-15 consumers (4x4 grid of 32x32 tiles), warp 16 producer.
#define KT 64
#define ROWB 144
#define TILEB (128 * ROWB)
#define NSTG 5
#define GM_SMEM (1024 + NSTG * 2 * TILEB)   // 185344 B

__global__ __launch_bounds__(544, 1) void gemm_mma(
    const __half* __restrict__ A, const __half* __restrict__ B,
    const float* __restrict__ bias, float* __restrict__ C,
    int Ndim, int Kp)
{
    extern __shared__ char smraw[];
    const uint32_t sb = smem_u32(smraw);
    const uint32_t dat = sb + 1024;
    const int tid = threadIdx.x;
    const int wid = tid >> 5, lane = tid & 31;
    const int brow = blockIdx.y * 128, bcol = blockIdx.x * 128;
    const int NT = Kp / KT;

    if (tid == 0) {
        #pragma unroll
        for (int s = 0; s < NSTG; s++) {
            MBAR_INIT(sb + s * 16, 32);
            MBAR_INIT(sb + s * 16 + 8, 16);
        }
    }
    __syncthreads();

    if (wid == 16) {
        int pst = 0, pph = 1;
        for (int kt = 0; kt < NT; kt++) {
            MBAR_WAIT(sb + pst * 16 + 8, pph);
            const __half* Ag = A + (size_t)brow * Kp + kt * KT;
            const __half* Bg = B + (size_t)bcol * Kp + kt * KT;
            uint32_t ab = dat + pst * (2 * TILEB);
            #pragma unroll
            for (int i = 0; i < 32; i++) {
                int chunk = lane + i * 32;
                int r = chunk >> 3, c = chunk & 7;
                uint32_t so = (uint32_t)(r * ROWB + c * 16);
                cpa16(ab + so, Ag + (size_t)r * Kp + c * 8);
                cpa16(ab + TILEB + so, Bg + (size_t)r * Kp + c * 8);
            }
            MBAR_ARRIVE_CP(sb + pst * 16);
            pst++; if (pst == NSTG) { pst = 0; pph ^= 1; }
        }
        return;
    }

    const int warpM = (wid >> 2) * 32;
    const int warpN = (wid & 3) * 32;
    const int lm = lane & 15, lh = lane >> 4;

    float acc[2][4][4];
    #pragma unroll
    for (int i = 0; i < 2; i++)
        #pragma unroll
        for (int j = 0; j < 4; j++)
            #pragma unroll
            for (int e = 0; e < 4; e++) acc[i][j][e] = 0.f;

    int cst = 0, cph = 0;
    for (int kt = 0; kt < NT; kt++) {
        MBAR_WAIT(sb + cst * 16, cph);

        uint32_t ab = dat + cst * (2 * TILEB);
        uint32_t bb = ab + TILEB;
        uint32_t aAddr = ab + (uint32_t)((warpM + lm) * ROWB + lh * 16);
        uint32_t bAddr = bb + (uint32_t)((warpN + lm) * ROWB + lh * 16);

        #pragma unroll
        for (int ks = 0; ks < 4; ks++) {
            uint32_t afr[2][4];
            #pragma unroll
            for (int mf = 0; mf < 2; mf++)
                ldm4(aAddr + mf * 16 * ROWB + ks * 32,
                     afr[mf][0], afr[mf][1], afr[mf][2], afr[mf][3]);
            uint32_t bfr[4][2];
            #pragma unroll
            for (int nb = 0; nb < 2; nb++) {
                uint32_t r0, r1, r2, r3;
                ldm4(bAddr + nb * 16 * ROWB + ks * 32, r0, r1, r2, r3);
                bfr[nb * 2 + 0][0] = r0; bfr[nb * 2 + 0][1] = r2;
                bfr[nb * 2 + 1][0] = r1; bfr[nb * 2 + 1][1] = r3;
            }
            #pragma unroll
            for (int mf = 0; mf < 2; mf++)
                #pragma unroll
                for (int nf = 0; nf < 4; nf++)
                    mma_f16(acc[mf][nf], afr[mf], bfr[nf][0], bfr[nf][1]);
        }

        if (lane == 0) MBAR_ARRIVE(sb + cst * 16 + 8);
        cst++; if (cst == NSTG) { cst = 0; cph ^= 1; }
    }

    #pragma unroll
    for (int mf = 0; mf < 2; mf++) {
        int grow = brow + warpM + mf * 16 + (lane >> 2);
        #pragma unroll
        for (int nf = 0; nf < 4; nf++) {
            int gcol = bcol + warpN + nf * 8 + (lane & 3) * 2;
            float bx = bias[gcol], by = bias[gcol + 1];
            float* d = acc[mf][nf];
            float2 v0 = {d[0] + bx, d[1] + by};
            float2 v1 = {d[2] + bx, d[3] + by};
            *(float2*)&C[(size_t)grow * Ndim + gcol] = v0;
            *(float2*)&C[(size_t)(grow + 8) * Ndim + gcol] = v1;
        }
    }
}

// ============ RoPE + fp16 split (q pre-scaled by 0.125*log2 e) ============
__global__ __launch_bounds__(256) void rope_split_kernel()
{
    int idx = blockIdx.x * blockDim.x + threadIdx.x;
    int i = idx & 31;
    int s = (idx >> 5)  & (Sn - 1);
    int h = (idx >> 15) & (Hn - 1);
    int b =  idx >> 19;

    const float* row = g_qkv + (size_t)(b * Sn + s) * N1;
    int base = h * Dn;

    float inv = expf(-(logf(10000.f) / Dn) * (2.f * i));
    float ang = (float)s * inv;
    float sn, cs;
    sincosf(ang, &sn, &cs);

    float q1 = row[0*Cn + base + i];
    float q2 = row[0*Cn + base + i + 32];
    float k1 = row[1*Cn + base + i];
    float k2 = row[1*Cn + base + i + 32];
    float v1 = row[2*Cn + base + i];
    float v2 = row[2*Cn + base + i + 32];

    const float QS = 0.18033688011112042f;  // 0.125 * log2(e)

    float qa = (q1 * cs - q2 * sn) * QS;
    float qb = (q2 * cs + q1 * sn) * QS;
    float ka = k1 * cs - k2 * sn;
    float kb = k2 * cs + k1 * sn;

    size_t o = ((size_t)(b * Hn + h) * Sn + s) * Dn;
    __half hh, ll;
    split2h(qa, hh, ll); g_qh[o + i] = hh;      g_ql[o + i] = ll;
    split2h(qb, hh, ll); g_qh[o + i + 32] = hh; g_ql[o + i + 32] = ll;
    g_kh[o + i]      = __float2half_rn(ka);
    g_kh[o + i + 32] = __float2half_rn(kb);
    g_vh[o + i]      = __float2half_rn(v1);
    g_vh[o + i + 32] = __float2half_rn(v2);
}

// ============ HMMA flash attention (fp16 2-product) ============
#define AT_ROWB 144
#define AT_TILE (128 * AT_ROWB)
#define AT_STAGE (2 * AT_TILE)                 // kh + vh
#define AT_SMEM (2 * AT_TILE + 2 * AT_STAGE)   // Q(hi,lo) + 2 stages = 110592

__global__ __launch_bounds__(256, 1) void attn_mma()
{
    extern __shared__ char smraw[];
    const uint32_t sb = smem_u32(smraw);
    const int tid = threadIdx.x, wid = tid >> 5, lane = tid & 31;
    const int bh = blockIdx.y;
    const int q0 = blockIdx.x * 128;
    const size_t bhoff = (size_t)bh * Sn * Dn;

    const uint32_t qhi_s = sb;
    const uint32_t qlo_s = sb + AT_TILE;
    const uint32_t stage0 = sb + 2 * AT_TILE;

    {
        const __half* Qh = g_qh + bhoff + (size_t)q0 * Dn;
        const __half* Ql = g_ql + bhoff + (size_t)q0 * Dn;
        #pragma unroll
        for (int i = 0; i < 4; i++) {
            int slot = i * 256 + tid;
            int r = slot >> 3, c = slot & 7;
            uint32_t so = (uint32_t)(r * AT_ROWB + c * 16);
            cpa16(qhi_s + so, Qh + (size_t)r * Dn + c * 8);
            cpa16(qlo_s + so, Ql + (size_t)r * Dn + c * 8);
        }
    }
    auto load_kv = [&](int t, int buf) {
        uint32_t st = stage0 + buf * AT_STAGE;
        const __half* Kh = g_kh + bhoff + (size_t)t * 128 * Dn;
        const __half* Vh = g_vh + bhoff + (size_t)t * 128 * Dn;
        #pragma unroll
        for (int i = 0; i < 4; i++) {
            int slot = i * 256 + tid;
            int r = slot >> 3, c = slot & 7;
            uint32_t so = (uint32_t)(r * AT_ROWB + c * 16);
            size_t go = (size_t)r * Dn + c * 8;
            cpa16(st + so, Kh + go);
            cpa16(st + AT_TILE + so, Vh + go);
        }
        asm volatile("cp.async.commit_group;" ::: "memory");
    };
    load_kv(0, 0);

    asm volatile("cp.async.wait_group 0;" ::: "memory");
    __syncthreads();

    const int lm = lane & 15, lh = lane >> 4;
    uint32_t qh[4][4], ql[4][4];
    {
        uint32_t a = (uint32_t)((wid * 16 + lm) * AT_ROWB + lh * 16);
        #pragma unroll
        for (int ks = 0; ks < 4; ks++) {
            ldm4(qhi_s + a + ks * 32, qh[ks][0], qh[ks][1], qh[ks][2], qh[ks][3]);
            ldm4(qlo_s + a + ks * 32, ql[ks][0], ql[ks][1], ql[ks][2], ql[ks][3]);
        }
    }

    float o[8][4];
    #pragma unroll
    for (int i = 0; i < 8; i++)
        #pragma unroll
        for (int e = 0; e < 4; e++) o[i][e] = 0.f;
    float m0 = -1e30f, m1 = -1e30f, ps0 = 0.f, ps1 = 0.f;

    for (int t = 0; t < 8; t++) {
        if (t > 0) {
            asm volatile("cp.async.wait_group 0;" ::: "memory");
            __syncthreads();
        }
        if (t < 7) load_kv(t + 1, (t + 1) & 1);

        uint32_t st = stage0 + (t & 1) * AT_STAGE;
        uint32_t kh_s = st, vh_s = st + AT_TILE;

        float sc[16][4];
        #pragma unroll
        for (int f = 0; f < 16; f++)
            #pragma unroll
            for (int e = 0; e < 4; e++) sc[f][e] = 0.f;

        uint32_t bbase = (uint32_t)(lm * AT_ROWB + lh * 16);
        #pragma unroll
        for (int nb = 0; nb < 8; nb++) {
            uint32_t ah = kh_s + bbase + nb * 16 * AT_ROWB;
            #pragma unroll
            for (int ks = 0; ks < 4; ks++) {
                uint32_t h0, h1, h2, h3;
                ldm4(ah + ks * 32, h0, h1, h2, h3);
                mma_f16(sc[2 * nb],     qh[ks], h0, h2);
                mma_f16(sc[2 * nb],     ql[ks], h0, h2);
                mma_f16(sc[2 * nb + 1], qh[ks], h1, h3);
                mma_f16(sc[2 * nb + 1], ql[ks], h1, h3);
            }
        }

        float mx0 = -1e30f, mx1 = -1e30f;
        #pragma unroll
        for (int f = 0; f < 16; f++) {
            mx0 = fmaxf(mx0, fmaxf(sc[f][0], sc[f][1]));
            mx1 = fmaxf(mx1, fmaxf(sc[f][2], sc[f][3]));
        }
        mx0 = fmaxf(mx0, __shfl_xor_sync(0xffffffffu, mx0, 1));
        mx0 = fmaxf(mx0, __shfl_xor_sync(0xffffffffu, mx0, 2));
        mx1 = fmaxf(mx1, __shfl_xor_sync(0xffffffffu, mx1, 1));
        mx1 = fmaxf(mx1, __shfl_xor_sync(0xffffffffu, mx1, 2));

        float mn0 = fmaxf(m0, mx0), mn1 = fmaxf(m1, mx1);
        float f0 = ex2(m0 - mn0), f1 = ex2(m1 - mn1);
        m0 = mn0; m1 = mn1;
        ps0 *= f0; ps1 *= f1;
        #pragma unroll
        for (int nf = 0; nf < 8; nf++) {
            o[nf][0] *= f0; o[nf][1] *= f0;
            o[nf][2] *= f1; o[nf][3] *= f1;
        }

        uint32_t pa_hi[8][4], pa_lo[8][4];
        #pragma unroll
        for (int t2 = 0; t2 < 8; t2++) {
            #pragma unroll
            for (int half = 0; half < 2; half++) {
                int f = 2 * t2 + half;
                float p0 = ex2(sc[f][0] - m0);
                float p1 = ex2(sc[f][1] - m0);
                float p2 = ex2(sc[f][2] - m1);
                float p3 = ex2(sc[f][3] - m1);
                ps0 += p0 + p1; ps1 += p2 + p3;
                __half h0, l0, h1, l1, h2, l2, h3, l3;
                split2h(p0, h0, l0); split2h(p1, h1, l1);
                split2h(p2, h2, l2); split2h(p3, h3, l3);
                pa_hi[t2][half * 2 + 0] = packh(h0, h1);
                pa_hi[t2][half * 2 + 1] = packh(h2, h3);
                pa_lo[t2][half * 2 + 0] = packh(l0, l1);
                pa_lo[t2][half * 2 + 1] = packh(l2, l3);
            }
        }

        #pragma unroll
        for (int t2 = 0; t2 < 8; t2++) {
            uint32_t vrow = (uint32_t)((t2 * 16 + lm) * AT_ROWB + lh * 16);
            #pragma unroll
            for (int dn = 0; dn < 4; dn++) {
                uint32_t h0, h1, h2, h3;
                ldm4t(vh_s + vrow + dn * 32, h0, h1, h2, h3);
                mma_f16(o[2 * dn],     pa_hi[t2], h0, h1);
                mma_f16(o[2 * dn],     pa_lo[t2], h0, h1);
                mma_f16(o[2 * dn + 1], pa_hi[t2], h2, h3);
                mma_f16(o[2 * dn + 1], pa_lo[t2], h2, h3);
            }
        }
    }

    ps0 += __shfl_xor_sync(0xffffffffu, ps0, 1);
    ps0 += __shfl_xor_sync(0xffffffffu, ps0, 2);
    ps1 += __shfl_xor_sync(0xffffffffu, ps1, 1);
    ps1 += __shfl_xor_sync(0xffffffffu, ps1, 2);
    float inv0 = 1.f / ps0, inv1 = 1.f / ps1;

    const int bidx = bh >> 4, hidx = bh & 15;
    const int grow = bidx * Sn + q0 + wid * 16 + (lane >> 2);

    #pragma unroll
    for (int nf = 0; nf < 8; nf++) {
        int col = hidx * 64 + nf * 8 + (lane & 3) * 2;
        float v0 = o[nf][0] * inv0, v1 = o[nf][1] * inv0;
        float v2 = o[nf][2] * inv1, v3 = o[nf][3] * inv1;
        __half h0, l0, h1, l1, h2, l2, h3, l3;
        split2h(v0, h0, l0); split2h(v1, h1, l1);
        split2h(v2, h2, l2); split2h(v3, h3, l3);
        uint32_t hp0 = packh(h0, h1), lp0 = packh(l0, l1);
        uint32_t hp1 = packh(h2, h3), lp1 = packh(l2, l3);
        size_t r0 = (size_t)grow * KP + col;
        size_t r1 = (size_t)(grow + 8) * KP + col;
        *(uint32_t*)&g_A2[r0]        = hp0;
        *(uint32_t*)&g_A2[r0 + 1024] = lp0;
        *(uint32_t*)&g_A2[r1]        = hp1;
        *(uint32_t*)&g_A2[r1 + 1024] = lp1;
    }
}

// ============ launch ============
extern "C" void kernel_launch(void* const* d_in, const int* in_sizes, int n_in,
                              void* d_out, int out_size)
{
    const float* x      = (const float*)d_in[0];
    const float* W_qkv  = (const float*)d_in[1];
    const float* b_qkv  = (const float*)d_in[2];
    const float* W_proj = (const float*)d_in[3];
    const float* b_proj = (const float*)d_in[4];
    float* out = (float*)d_out;

    cudaFuncSetAttribute(gemm_mma, cudaFuncAttributeMaxDynamicSharedMemorySize, GM_SMEM);
    cudaFuncSetAttribute(attn_mma, cudaFuncAttributeMaxDynamicSharedMemorySize, AT_SMEM);

    float* p_qkv;
    __half *p_A2, *p_B2, *p_B2p;
    cudaGetSymbolAddress((void**)&p_qkv, g_qkv);
    cudaGetSymbolAddress((void**)&p_A2, g_A2);
    cudaGetSymbolAddress((void**)&p_B2, g_B2);
    cudaGetSymbolAddress((void**)&p_B2p, g_B2p);

    // launches ordered so the QKV GEMM is #4 (ncu captures launch 4)
    conv_A<<<(Mn * Cn) / 256, 256>>>(x, p_A2, Cn);                        // 1
    { dim3 g(Cn / 32, N1 / 32); conv_B<<<g, 256>>>(W_qkv, p_B2, Cn, N1); }   // 2
    { dim3 g(Cn / 32, Cn / 32); conv_B<<<g, 256>>>(W_proj, p_B2p, Cn, Cn); } // 3
    { dim3 g(N1 / 128, Mn / 128);
      gemm_mma<<<g, 544, GM_SMEM>>>(p_A2, p_B2, b_qkv, p_qkv, N1, KP); }     // 4 (profiled)
    rope_split_kernel<<<(Bn * Hn * Sn * 32) / 256, 256>>>();                 // 5
    { dim3 g(Sn / 128, Bn * Hn); attn_mma<<<g, 256, AT_SMEM>>>(); }          // 6
    { dim3 g(Cn / 128, Mn / 128);
      gemm_mma<<<g, 544, GM_SMEM>>>(p_A2, p_B2p, b_proj, out, Cn, KP); }     // 7
}